// round 6
// baseline (speedup 1.0000x reference)
#include <cuda_runtime.h>
#include <cuda_bf16.h>
#include <cstdint>
#include <cstddef>

#define S_LEN 2048
#define DIM   2048
#define HEADS 16
#define HD    128
#define BATCH 4

// Scratch (allocation-free rule: __device__ globals)
#define PLANE_ELEMS ((size_t)BATCH * HEADS * S_LEN * HD)
__device__ __nv_bfloat16 g_qhi[PLANE_ELEMS], g_qlo[PLANE_ELEMS];
__device__ __nv_bfloat16 g_khi[PLANE_ELEMS], g_klo[PLANE_ELEMS];
__device__ __nv_bfloat16 g_vhi[PLANE_ELEMS], g_vlo[PLANE_ELEMS];
__device__ __nv_bfloat16 g_xhi[(size_t)BATCH * S_LEN * DIM], g_xlo[(size_t)BATCH * S_LEN * DIM];
__device__ __nv_bfloat16 g_ahi[(size_t)BATCH * S_LEN * DIM], g_alo[(size_t)BATCH * S_LEN * DIM];
__device__ __nv_bfloat16 g_wqhi[(size_t)(3 * DIM) * DIM], g_wqlo[(size_t)(3 * DIM) * DIM];
__device__ __nv_bfloat16 g_wohi[(size_t)DIM * DIM], g_wolo[(size_t)DIM * DIM];

// ---------------------------------------------------------------------------
// helpers
// ---------------------------------------------------------------------------
__device__ __forceinline__ uint32_t smem_to_u32(const void* p) {
    uint32_t a;
    asm("{ .reg .u64 t; cvta.to.shared.u64 t, %1; cvt.u32.u64 %0, t; }"
        : "=r"(a) : "l"(p));
    return a;
}

__device__ __forceinline__ void ldsm4(uint32_t* r, uint32_t addr) {
    asm volatile("ldmatrix.sync.aligned.m8n8.x4.shared.b16 {%0,%1,%2,%3}, [%4];"
                 : "=r"(r[0]), "=r"(r[1]), "=r"(r[2]), "=r"(r[3]) : "r"(addr));
}

__device__ __forceinline__ void ldsm4t(uint32_t* r, uint32_t addr) {
    asm volatile("ldmatrix.sync.aligned.m8n8.x4.trans.shared.b16 {%0,%1,%2,%3}, [%4];"
                 : "=r"(r[0]), "=r"(r[1]), "=r"(r[2]), "=r"(r[3]) : "r"(addr));
}

__device__ __forceinline__ void mma_bf16(float* d, const uint32_t* a, const uint32_t* b) {
    asm volatile(
        "mma.sync.aligned.m16n8k16.row.col.f32.bf16.bf16.f32 "
        "{%0,%1,%2,%3}, {%4,%5,%6,%7}, {%8,%9}, {%0,%1,%2,%3};"
        : "+f"(d[0]), "+f"(d[1]), "+f"(d[2]), "+f"(d[3])
        : "r"(a[0]), "r"(a[1]), "r"(a[2]), "r"(a[3]), "r"(b[0]), "r"(b[1]));
}

// pack (x0,x1) -> bf16x2 hi (low half = x0) and bf16x2 lo (residuals)
__device__ __forceinline__ void split_bf16x2(float x0, float x1,
                                             uint32_t& hi, uint32_t& lo) {
    asm("cvt.rn.bf16x2.f32 %0, %1, %2;" : "=r"(hi) : "f"(x1), "f"(x0));
    float h0 = __uint_as_float(hi << 16);
    float h1 = __uint_as_float(hi & 0xffff0000u);
    float r0 = x0 - h0;
    float r1 = x1 - h1;
    asm("cvt.rn.bf16x2.f32 %0, %1, %2;" : "=r"(lo) : "f"(r1), "f"(r0));
}

#define CP_ASYNC16(dst, src) \
    asm volatile("cp.async.cg.shared.global [%0], [%1], 16;" \
                 :: "r"(dst), "l"(src) : "memory")
#define CP_COMMIT() asm volatile("cp.async.commit_group;" ::: "memory")
#define CP_WAIT1()  asm volatile("cp.async.wait_group 1;" ::: "memory")
#define CP_WAIT2()  asm volatile("cp.async.wait_group 2;" ::: "memory")

// ---------------------------------------------------------------------------
// Elementwise split: fp32 -> bf16 hi/lo planes (float2 granular)
// ---------------------------------------------------------------------------
__global__ __launch_bounds__(256) void split_kernel(
    const float* __restrict__ in,
    __nv_bfloat16* __restrict__ hi, __nv_bfloat16* __restrict__ lo, size_t n2)
{
    size_t i = (size_t)blockIdx.x * blockDim.x + threadIdx.x;
    size_t stride = (size_t)gridDim.x * blockDim.x;
    for (; i < n2; i += stride) {
        float2 v = *(const float2*)(in + 2 * i);
        uint32_t h, l;
        split_bf16x2(v.x, v.y, h, l);
        *(uint32_t*)(hi + 2 * i) = h;
        *(uint32_t*)(lo + 2 * i) = l;
    }
}

// ---------------------------------------------------------------------------
// Transpose + split: fp32 in[R][C] -> bf16 hi/lo out[C][R]
// out[bx+x][by+2*cp .. +1] = in[by+2*cp][bx+x], in[by+2*cp+1][bx+x]
// ---------------------------------------------------------------------------
__global__ __launch_bounds__(256) void transpose_split2_kernel(
    const float* __restrict__ in,
    __nv_bfloat16* __restrict__ hi, __nv_bfloat16* __restrict__ lo, int R, int C)
{
    __shared__ float t[32][33];
    int bx = blockIdx.x * 32;   // col block in `in` -> row block in out
    int by = blockIdx.y * 32;   // row block in `in` -> col block in out
    int x = threadIdx.x, y = threadIdx.y;   // 32 x 8
#pragma unroll
    for (int j = 0; j < 32; j += 8)
        t[y + j][x] = in[(size_t)(by + y + j) * C + bx + x];
    __syncthreads();
#pragma unroll
    for (int jj = 0; jj < 2; jj++) {
        int cp = y + 8 * jj;                 // 0..15 col pair index
        uint32_t h, l;
        split_bf16x2(t[cp * 2][x], t[cp * 2 + 1][x], h, l);
        size_t o = (size_t)(bx + x) * R + by + cp * 2;
        *(uint32_t*)(hi + o) = h;
        *(uint32_t*)(lo + o) = l;
    }
}

// ---------------------------------------------------------------------------
// Pure-bf16 plane GEMM: C = A @ B^T (+bias), A/B pre-split hi/lo planes [*,K]
// 128x128 tile, BK=32, 256 threads, 3-stage cp.async pipeline.
// Stage layout (row stride 80B): Ahi@0  Alo@10240  Bhi@20480  Blo@30720
// ---------------------------------------------------------------------------
#define GSTRIDE      80
#define GSTAGE_BYTES 40960
#define GSMEM_BYTES  (3 * GSTAGE_BYTES)

#define GEMM_PL_BODY                                                          \
    extern __shared__ __align__(1024) char smem[];                            \
    const uint32_t sb = smem_to_u32(smem);                                    \
    const int tid = threadIdx.x;                                              \
    const int wid = tid >> 5, lid = tid & 31;                                 \
    const int wm = wid >> 1;                                                  \
    const int wn = wid & 1;                                                   \
    const int m0 = blockIdx.y * 128;                                          \
    const int n0 = blockIdx.x * 128;                                          \
    const uint32_t aBase = (uint32_t)((wm * 32 + (lid & 15)) * GSTRIDE + (lid >> 4) * 16); \
    const uint32_t bBase = (uint32_t)((wn * 64 + ((lid >> 1) & 8) + (lid & 7)) * GSTRIDE \
                                      + ((lid & 8) << 1));                    \
    const int lrow = tid >> 1;                                                \
    const int lc0 = (tid & 1) * 2;                                            \
    float acc[2][8][4];                                                       \
    _Pragma("unroll")                                                         \
    for (int mf = 0; mf < 2; mf++)                                            \
        _Pragma("unroll")                                                     \
        for (int nf = 0; nf < 8; nf++)                                        \
            _Pragma("unroll")                                                 \
            for (int q = 0; q < 4; q++) acc[mf][nf][q] = 0.f;                 \
    const int niter = K >> 5;                                                 \
    auto issue = [&](int i, int s) {                                          \
        const int k0 = i << 5;                                                \
        const uint32_t base = sb + s * GSTAGE_BYTES;                          \
        const uint32_t so = (uint32_t)(lrow * GSTRIDE + lc0 * 16);            \
        const size_t ga = (size_t)(m0 + lrow) * K + k0 + lc0 * 8;             \
        const size_t gb = (size_t)(n0 + lrow) * K + k0 + lc0 * 8;             \
        CP_ASYNC16(base + so,              (const char*)(Ahi + ga));          \
        CP_ASYNC16(base + so + 16,         (const char*)(Ahi + ga + 8));      \
        CP_ASYNC16(base + 10240 + so,      (const char*)(Alo + ga));          \
        CP_ASYNC16(base + 10240 + so + 16, (const char*)(Alo + ga + 8));      \
        CP_ASYNC16(base + 20480 + so,      (const char*)(Bhi + gb));          \
        CP_ASYNC16(base + 20480 + so + 16, (const char*)(Bhi + gb + 8));      \
        CP_ASYNC16(base + 30720 + so,      (const char*)(Blo + gb));          \
        CP_ASYNC16(base + 30720 + so + 16, (const char*)(Blo + gb + 8));      \
    };                                                                        \
    issue(0, 0); CP_COMMIT();                                                 \
    if (niter > 1) { issue(1, 1); CP_COMMIT(); }                              \
    for (int i = 0; i < niter; i++) {                                         \
        const int s = i % 3;                                                  \
        if (i + 2 < niter) issue(i + 2, (i + 2) % 3);                         \
        CP_COMMIT();                                                          \
        CP_WAIT2();                                                           \
        __syncthreads();                                                      \
        const uint32_t sA = sb + s * GSTAGE_BYTES;                            \
        _Pragma("unroll")                                                     \
        for (int kstep = 0; kstep < 2; kstep++) {                             \
            const uint32_t koff = kstep * 32;                                 \
            uint32_t ahi[2][4], alo[2][4];                                    \
            ldsm4(ahi[0], sA + aBase + koff);                                 \
            ldsm4(ahi[1], sA + aBase + 16 * GSTRIDE + koff);                  \
            ldsm4(alo[0], sA + 10240 + aBase + koff);                         \
            ldsm4(alo[1], sA + 10240 + aBase + 16 * GSTRIDE + koff);          \
            uint32_t bhi[8][2], blo[8][2];                                    \
            _Pragma("unroll")                                                 \
            for (int t2 = 0; t2 < 4; t2++) {                                  \
                uint32_t r[4];                                                \
                ldsm4(r, sA + 20480 + bBase + t2 * 16 * GSTRIDE + koff);      \
                bhi[2 * t2][0] = r[0]; bhi[2 * t2][1] = r[1];                 \
                bhi[2 * t2 + 1][0] = r[2]; bhi[2 * t2 + 1][1] = r[3];         \
                ldsm4(r, sA + 30720 + bBase + t2 * 16 * GSTRIDE + koff);      \
                blo[2 * t2][0] = r[0]; blo[2 * t2][1] = r[1];                 \
                blo[2 * t2 + 1][0] = r[2]; blo[2 * t2 + 1][1] = r[3];         \
            }                                                                 \
            _Pragma("unroll")                                                 \
            for (int mf = 0; mf < 2; mf++)                                    \
                _Pragma("unroll")                                             \
                for (int nf = 0; nf < 8; nf++) {                              \
                    mma_bf16(acc[mf][nf], ahi[mf], bhi[nf]);                  \
                    mma_bf16(acc[mf][nf], ahi[mf], blo[nf]);                  \
                    mma_bf16(acc[mf][nf], alo[mf], bhi[nf]);                  \
                }                                                             \
        }                                                                     \
        __syncthreads();                                                      \
    }

// fp32 output GEMM (output projection)
__global__ __launch_bounds__(256, 1) void gemm_pl_out_kernel(
    const __nv_bfloat16* __restrict__ Ahi, const __nv_bfloat16* __restrict__ Alo,
    const __nv_bfloat16* __restrict__ Bhi, const __nv_bfloat16* __restrict__ Blo,
    const float* __restrict__ bias, float* __restrict__ C, int N, int K)
{
    GEMM_PL_BODY
    const int erow = m0 + wm * 32 + (lid >> 2);
    const int ecol0 = n0 + wn * 64 + (lid & 3) * 2;
#pragma unroll
    for (int mf = 0; mf < 2; mf++) {
#pragma unroll
        for (int nf = 0; nf < 8; nf++) {
            int col = ecol0 + nf * 8;
            float2 bz = *(const float2*)(bias + col);
            float2 v0, v1;
            v0.x = acc[mf][nf][0] + bz.x; v0.y = acc[mf][nf][1] + bz.y;
            v1.x = acc[mf][nf][2] + bz.x; v1.y = acc[mf][nf][3] + bz.y;
            size_t r0 = (size_t)(erow + mf * 16) * N + col;
            *(float2*)(C + r0) = v0;
            *(float2*)(C + r0 + 8 * N) = v1;
        }
    }
}

// QKV GEMM: writes bf16 hi/lo planes (Q pre-scaled)
__global__ __launch_bounds__(256, 1) void gemm_pl_qkv_kernel(
    const __nv_bfloat16* __restrict__ Ahi, const __nv_bfloat16* __restrict__ Alo,
    const __nv_bfloat16* __restrict__ Bhi, const __nv_bfloat16* __restrict__ Blo,
    const float* __restrict__ bias,
    __nv_bfloat16* __restrict__ qhi, __nv_bfloat16* __restrict__ qlo,
    __nv_bfloat16* __restrict__ khi, __nv_bfloat16* __restrict__ klo,
    __nv_bfloat16* __restrict__ vhi, __nv_bfloat16* __restrict__ vlo,
    int N, int K)
{
    GEMM_PL_BODY
    const int t = n0 >> 11;                 // 0=Q 1=K 2=V
    const int head = (n0 >> 7) & (HEADS - 1);
    __nv_bfloat16 *phi, *plo;
    if (t == 0)      { phi = qhi; plo = qlo; }
    else if (t == 1) { phi = khi; plo = klo; }
    else             { phi = vhi; plo = vlo; }
    const float sc = (t == 0) ? 0.08838834764831845f : 1.0f;
    const int erow = m0 + wm * 32 + (lid >> 2);
    const int lcol0 = wn * 64 + (lid & 3) * 2;
#pragma unroll
    for (int mf = 0; mf < 2; mf++) {
        int tok0 = erow + mf * 16;
        int b = tok0 >> 11;
        int s0 = tok0 & 2047;
        size_t pb = ((size_t)(b * HEADS + head) * S_LEN) * HD;
#pragma unroll
        for (int nf = 0; nf < 8; nf++) {
            int lc = lcol0 + nf * 8;
            float2 bz = *(const float2*)(bias + n0 + lc);
            float v0 = (acc[mf][nf][0] + bz.x) * sc;
            float v1 = (acc[mf][nf][1] + bz.y) * sc;
            float v2 = (acc[mf][nf][2] + bz.x) * sc;
            float v3 = (acc[mf][nf][3] + bz.y) * sc;
            uint32_t h, l;
            split_bf16x2(v0, v1, h, l);
            size_t p0 = pb + (size_t)s0 * HD + lc;
            *(uint32_t*)(phi + p0) = h;
            *(uint32_t*)(plo + p0) = l;
            split_bf16x2(v2, v3, h, l);
            size_t p1 = pb + (size_t)(s0 + 8) * HD + lc;
            *(uint32_t*)(phi + p1) = h;
            *(uint32_t*)(plo + p1) = l;
        }
    }
}

// ---------------------------------------------------------------------------
// Tensor-core flash attention (bf16 3-pass split) with segment+causal mask.
// grid (32, HEADS, BATCH), 256 threads = 8 warps (4 m-slabs x 2 key-slabs).
// Output: bf16 hi/lo planes of the normalized attention output.
// ---------------------------------------------------------------------------
#define AQ_STRIDE 272                 // smem bytes per row (136 halves)
#define SQHI 0
#define SQLO 17408
#define SSTAGE0 34816
#define SSTAGE_BYTES 69632            // Khi,Klo,Vhi,Vlo
#define SKHI 0
#define SKLO 17408
#define SVHI 34816
#define SVLO 52224
#define SKID  174080                  // + stage*256
#define SPMAX 174592
#define SLSUM 175104
#define ATTN_SMEM 175616

__global__ __launch_bounds__(256, 1) void attn_mma_kernel(
    const int* __restrict__ ids,
    __nv_bfloat16* __restrict__ ohi, __nv_bfloat16* __restrict__ olo,
    const __nv_bfloat16* __restrict__ qhi, const __nv_bfloat16* __restrict__ qlo,
    const __nv_bfloat16* __restrict__ khi, const __nv_bfloat16* __restrict__ klo,
    const __nv_bfloat16* __restrict__ vhi, const __nv_bfloat16* __restrict__ vlo)
{
    extern __shared__ __align__(1024) char smem[];
    const uint32_t sb = smem_to_u32(smem);
    const int tid = threadIdx.x;
    const int lane = tid & 31, wid = tid >> 5;
    const int wm = wid >> 1, wn = wid & 1;
    const int b = blockIdx.z, h = blockIdx.y;
    const int qt = gridDim.x - 1 - blockIdx.x;       // big tiles first
    const int q0 = qt * 64;
    const size_t pbase = (size_t)(b * HEADS + h) * S_LEN * HD;
    const int* bids = ids + b * S_LEN;

    const int lr = lane >> 2;
    const int row0 = wm * 16 + lr, row1 = row0 + 8;
    const int qrow0 = q0 + row0, qrow1 = q0 + row1;
    const int qidv0 = bids[qrow0], qidv1 = bids[qrow1];
    const int qid_min = bids[q0];

    float* pmax = (float*)(smem + SPMAX);
    float* lsum = (float*)(smem + SLSUM);

    auto issue_tile = [&](int kb, int s) {
        const int k0 = kb * 64;
        const uint32_t stg = sb + SSTAGE0 + s * SSTAGE_BYTES;
#pragma unroll
        for (int j = 0; j < 4; j++) {
            int q = tid + 256 * j;
            int key = q >> 4, c16 = q & 15;
            uint32_t soff = (uint32_t)(key * AQ_STRIDE + c16 * 16);
            size_t goff = pbase + (size_t)(k0 + key) * HD + c16 * 8;
            CP_ASYNC16(stg + SKHI + soff, (const char*)(khi + goff));
            CP_ASYNC16(stg + SKLO + soff, (const char*)(klo + goff));
            CP_ASYNC16(stg + SVHI + soff, (const char*)(vhi + goff));
            CP_ASYNC16(stg + SVLO + soff, (const char*)(vlo + goff));
        }
        if (tid < 16)
            CP_ASYNC16(sb + SKID + s * 256 + tid * 16,
                       (const char*)(bids + k0 + tid * 4));
    };

    // ---- prologue: Q planes + tile 0 in cp.async group 0 ----
#pragma unroll
    for (int j = 0; j < 4; j++) {
        int q = tid + 256 * j;
        int key = q >> 4, c16 = q & 15;
        uint32_t soff = (uint32_t)(key * AQ_STRIDE + c16 * 16);
        size_t goff = pbase + (size_t)(q0 + key) * HD + c16 * 8;
        CP_ASYNC16(sb + SQHI + soff, (const char*)(qhi + goff));
        CP_ASYNC16(sb + SQLO + soff, (const char*)(qlo + goff));
    }
    issue_tile(0, 0);
    CP_COMMIT();

    float O[16][4];
#pragma unroll
    for (int nb = 0; nb < 16; nb++)
#pragma unroll
        for (int q = 0; q < 4; q++) O[nb][q] = 0.f;
    float m0r = -1e30f, m1r = -1e30f, l0r = 0.f, l1r = 0.f;

    const uint32_t qoffA = (uint32_t)((wm * 16 + (lane & 15)) * AQ_STRIDE + (lane >> 4) * 16);
    const uint32_t kBoff = (uint32_t)((wn * 32 + ((lane >> 1) & 8) + (lane & 7)) * AQ_STRIDE
                                      + ((lane & 8) << 1));
    const uint32_t vBoff = (uint32_t)((wn * 32 + ((lane >> 3) & 1) * 8 + (lane & 7)) * AQ_STRIDE
                                      + ((lane >> 4) & 1) * 16);

    const int nkb = qt;
    for (int kb = 0; kb <= nkb; kb++) {
        const int s = kb & 1;
        if (kb + 1 <= nkb) {
            bool skip_next = (bids[(kb + 1) * 64 + 63] < qid_min);
            if (!skip_next) issue_tile(kb + 1, s ^ 1);
        }
        CP_COMMIT();
        CP_WAIT1();
        __syncthreads();

        bool skip_cur = (bids[kb * 64 + 63] < qid_min);
        if (!skip_cur) {
            const uint32_t stg = sb + SSTAGE0 + s * SSTAGE_BYTES;
            const int k0 = kb * 64;

            // ---- S = Q K^T (3-pass split) ----
            float S[4][4];
#pragma unroll
            for (int nf = 0; nf < 4; nf++)
#pragma unroll
                for (int c = 0; c < 4; c++) S[nf][c] = 0.f;
#pragma unroll
            for (int ks = 0; ks < 8; ks++) {
                uint32_t ah[4], al[4];
                ldsm4(ah, sb + SQHI + qoffA + ks * 32);
                ldsm4(al, sb + SQLO + qoffA + ks * 32);
                uint32_t bh0[4], bh1[4], bl0[4], bl1[4];
                ldsm4(bh0, stg + SKHI + kBoff + ks * 32);
                ldsm4(bh1, stg + SKHI + kBoff + 16 * AQ_STRIDE + ks * 32);
                ldsm4(bl0, stg + SKLO + kBoff + ks * 32);
                ldsm4(bl1, stg + SKLO + kBoff + 16 * AQ_STRIDE + ks * 32);
                mma_bf16(S[0], ah, bh0 + 0); mma_bf16(S[0], ah, bl0 + 0); mma_bf16(S[0], al, bh0 + 0);
                mma_bf16(S[1], ah, bh0 + 2); mma_bf16(S[1], ah, bl0 + 2); mma_bf16(S[1], al, bh0 + 2);
                mma_bf16(S[2], ah, bh1 + 0); mma_bf16(S[2], ah, bl1 + 0); mma_bf16(S[2], al, bh1 + 0);
                mma_bf16(S[3], ah, bh1 + 2); mma_bf16(S[3], ah, bl1 + 2); mma_bf16(S[3], al, bh1 + 2);
            }

            // ---- mask + tile row max ----
            const uint32_t kidb = sb + SKID + s * 256;
            float mt0 = -1e30f, mt1 = -1e30f;
#pragma unroll
            for (int nf = 0; nf < 4; nf++) {
                int lc = wn * 32 + nf * 8 + 2 * (lane & 3);
                int kv0, kv1;
                asm volatile("ld.shared.v2.u32 {%0,%1}, [%2];"
                             : "=r"(kv0), "=r"(kv1) : "r"(kidb + lc * 4));
                int key = k0 + lc;
                if (key     > qrow0 || kv0 != qidv0) S[nf][0] = -1e30f;
                if (key + 1 > qrow0 || kv1 != qidv0) S[nf][1] = -1e30f;
                if (key     > qrow1 || kv0 != qidv1) S[nf][2] = -1e30f;
                if (key + 1 > qrow1 || kv1 != qidv1) S[nf][3] = -1e30f;
                mt0 = fmaxf(mt0, fmaxf(S[nf][0], S[nf][1]));
                mt1 = fmaxf(mt1, fmaxf(S[nf][2], S[nf][3]));
            }
            mt0 = fmaxf(mt0, __shfl_xor_sync(0xffffffffu, mt0, 1));
            mt0 = fmaxf(mt0, __shfl_xor_sync(0xffffffffu, mt0, 2));
            mt1 = fmaxf(mt1, __shfl_xor_sync(0xffffffffu, mt1, 1));
            mt1 = fmaxf(mt1, __shfl_xor_sync(0xffffffffu, mt1, 2));
            if ((lane & 3) == 0) {
                pmax[wn * 64 + row0] = mt0;
                pmax[wn * 64 + row1] = mt1;
            }
            __syncthreads();

            float mn0 = fmaxf(m0r, fmaxf(pmax[row0], pmax[64 + row0]));
            float mn1 = fmaxf(m1r, fmaxf(pmax[row1], pmax[64 + row1]));
            float f0 = __expf(m0r - mn0), f1 = __expf(m1r - mn1);
            m0r = mn0; m1r = mn1;

            float rs0 = 0.f, rs1 = 0.f;
#pragma unroll
            for (int nf = 0; nf < 4; nf++) {
                float p0 = (S[nf][0] < -1e29f) ? 0.f : __expf(S[nf][0] - mn0);
                float p1 = (S[nf][1] < -1e29f) ? 0.f : __expf(S[nf][1] - mn0);
                float p2 = (S[nf][2] < -1e29f) ? 0.f : __expf(S[nf][2] - mn1);
                float p3 = (S[nf][3] < -1e29f) ? 0.f : __expf(S[nf][3] - mn1);
                S[nf][0] = p0; S[nf][1] = p1; S[nf][2] = p2; S[nf][3] = p3;
                rs0 += p0 + p1; rs1 += p2 + p3;
            }
            rs0 += __shfl_xor_sync(0xffffffffu, rs0, 1);
            rs0 += __shfl_xor_sync(0xffffffffu, rs0, 2);
            rs1 += __shfl_xor_sync(0xffffffffu, rs1, 1);
            rs1 += __shfl_xor_sync(0xffffffffu, rs1, 2);
            l0r = l0r * f0 + rs0;
            l1r = l1r * f1 + rs1;

            // rescale O
#pragma unroll
            for (int nb = 0; nb < 16; nb++) {
                O[nb][0] *= f0; O[nb][1] *= f0;
                O[nb][2] *= f1; O[nb][3] *= f1;
            }

            // ---- O += P V (split P and V, 3-pass) ----
#pragma unroll
            for (int ks2 = 0; ks2 < 2; ks2++) {
                uint32_t ah[4], al[4];
                split_bf16x2(S[2 * ks2][0],     S[2 * ks2][1],     ah[0], al[0]);
                split_bf16x2(S[2 * ks2][2],     S[2 * ks2][3],     ah[1], al[1]);
                split_bf16x2(S[2 * ks2 + 1][0], S[2 * ks2 + 1][1], ah[2], al[2]);
                split_bf16x2(S[2 * ks2 + 1][2], S[2 * ks2 + 1][3], ah[3], al[3]);
                uint32_t ro = vBoff + ks2 * 16 * AQ_STRIDE;
#pragma unroll
                for (int nb = 0; nb < 8; nb++) {
                    uint32_t bh[4], bl[4];
                    ldsm4t(bh, stg + SVHI + ro + nb * 32);
                    ldsm4t(bl, stg + SVLO + ro + nb * 32);
                    mma_bf16(O[2 * nb],     ah, bh + 0);
                    mma_bf16(O[2 * nb],     ah, bl + 0);
                    mma_bf16(O[2 * nb],     al, bh + 0);
                    mma_bf16(O[2 * nb + 1], ah, bh + 2);
                    mma_bf16(O[2 * nb + 1], ah, bl + 2);
                    mma_bf16(O[2 * nb + 1], al, bh + 2);
                }
            }
        }
        __syncthreads();
    }

    // ---- epilogue: combine l across warp pairs, then O, then write planes ----
    if ((lane & 3) == 0) {
        lsum[wn * 64 + row0] = l0r;
        lsum[wn * 64 + row1] = l1r;
    }
    __syncthreads();
    float inv0 = 1.f / (lsum[row0] + lsum[64 + row0]);
    float inv1 = 1.f / (lsum[row1] + lsum[64 + row1]);

    if (wn == 1) {
#pragma unroll
        for (int nb = 0; nb < 16; nb++) {
            uint32_t off = (uint32_t)(wm * 8192 + lr * 512 + (nb * 8 + 2 * (lane & 3)) * 4);
            *(float2*)(smem + off) = make_float2(O[nb][0], O[nb][1]);
            *(float2*)(smem + off + 8 * 512) = make_float2(O[nb][2], O[nb][3]);
        }
    }
    __syncthreads();
    if (wn == 0) {
        const size_t g0 = ((size_t)b * S_LEN + qrow0) * DIM + h * HD;
        const size_t g1 = ((size_t)b * S_LEN + qrow1) * DIM + h * HD;
#pragma unroll
        for (int nb = 0; nb < 16; nb++) {
            int col = nb * 8 + 2 * (lane & 3);
            uint32_t off = (uint32_t)(wm * 8192 + lr * 512 + col * 4);
            float2 o0 = *(float2*)(smem + off);
            float2 o1 = *(float2*)(smem + off + 8 * 512);
            uint32_t hh, ll;
            split_bf16x2((O[nb][0] + o0.x) * inv0, (O[nb][1] + o0.y) * inv0, hh, ll);
            *(uint32_t*)(ohi + g0 + col) = hh;
            *(uint32_t*)(olo + g0 + col) = ll;
            split_bf16x2((O[nb][2] + o1.x) * inv1, (O[nb][3] + o1.y) * inv1, hh, ll);
            *(uint32_t*)(ohi + g1 + col) = hh;
            *(uint32_t*)(olo + g1 + col) = ll;
        }
    }
}

// ---------------------------------------------------------------------------
extern "C" void kernel_launch(void* const* d_in, const int* in_sizes, int n_in,
                              void* d_out, int out_size)
{
    const float* x    = (const float*)d_in[0];   // [4,2048,2048]
    const int*   ids  = (const int*)d_in[1];     // [4,2048]
    const float* Wqkv = (const float*)d_in[2];   // [2048,6144]
    const float* bqkv = (const float*)d_in[3];   // [6144]
    const float* Wo   = (const float*)d_in[4];   // [2048,2048]
    const float* bo   = (const float*)d_in[5];   // [2048]
    float* out = (float*)d_out;

    __nv_bfloat16 *qhi, *qlo, *khi, *klo, *vhi, *vlo;
    __nv_bfloat16 *xhi, *xlo, *ahi, *alo, *wqhi, *wqlo, *wohi, *wolo;
    cudaGetSymbolAddress((void**)&qhi, g_qhi);
    cudaGetSymbolAddress((void**)&qlo, g_qlo);
    cudaGetSymbolAddress((void**)&khi, g_khi);
    cudaGetSymbolAddress((void**)&klo, g_klo);
    cudaGetSymbolAddress((void**)&vhi, g_vhi);
    cudaGetSymbolAddress((void**)&vlo, g_vlo);
    cudaGetSymbolAddress((void**)&xhi, g_xhi);
    cudaGetSymbolAddress((void**)&xlo, g_xlo);
    cudaGetSymbolAddress((void**)&ahi, g_ahi);
    cudaGetSymbolAddress((void**)&alo, g_alo);
    cudaGetSymbolAddress((void**)&wqhi, g_wqhi);
    cudaGetSymbolAddress((void**)&wqlo, g_wqlo);
    cudaGetSymbolAddress((void**)&wohi, g_wohi);
    cudaGetSymbolAddress((void**)&wolo, g_wolo);

    cudaFuncSetAttribute(gemm_pl_out_kernel,
                         cudaFuncAttributeMaxDynamicSharedMemorySize, GSMEM_BYTES);
    cudaFuncSetAttribute(gemm_pl_qkv_kernel,
                         cudaFuncAttributeMaxDynamicSharedMemorySize, GSMEM_BYTES);
    cudaFuncSetAttribute(attn_mma_kernel,
                         cudaFuncAttributeMaxDynamicSharedMemorySize, ATTN_SMEM);

    const int M = BATCH * S_LEN;   // 8192

    // 0) pre-split x and weights (one-shot)
    split_kernel<<<1184, 256>>>(x, xhi, xlo, (size_t)M * DIM / 2);
    {
        dim3 blk(32, 8);
        transpose_split2_kernel<<<dim3(3 * DIM / 32, DIM / 32), blk>>>(Wqkv, wqhi, wqlo, DIM, 3 * DIM);
        transpose_split2_kernel<<<dim3(DIM / 32, DIM / 32), blk>>>(Wo, wohi, wolo, DIM, DIM);
    }
    // 1) QKV = x @ Wqkv + bqkv -> bf16 hi/lo planes (Q pre-scaled)
    {
        dim3 grid(3 * DIM / 128, M / 128);
        gemm_pl_qkv_kernel<<<grid, 256, GSMEM_BYTES>>>(
            xhi, xlo, wqhi, wqlo, bqkv, qhi, qlo, khi, klo, vhi, vlo, 3 * DIM, DIM);
    }
    // 2) flash attention -> bf16 hi/lo planes
    {
        dim3 grid(S_LEN / 64, HEADS, BATCH);
        attn_mma_kernel<<<grid, 256, ATTN_SMEM>>>(
            ids, ahi, alo, qhi, qlo, khi, klo, vhi, vlo);
    }
    // 3) out = attn @ Wo + bo  [8192, 2048] fp32
    {
        dim3 grid(DIM / 128, M / 128);
        gemm_pl_out_kernel<<<grid, 256, GSMEM_BYTES>>>(
            ahi, alo, wohi, wolo, bo, out, DIM, DIM);
    }
}

// round 7
// speedup vs baseline: 1.0008x; 1.0008x over previous
#include <cuda_runtime.h>
#include <cuda_bf16.h>
#include <cstdint>
#include <cstddef>

#define S_LEN 2048
#define DIM   2048
#define HEADS 16
#define HD    128
#define BATCH 4

// Scratch (allocation-free rule: __device__ globals)
#define PLANE_ELEMS ((size_t)BATCH * HEADS * S_LEN * HD)
__device__ __nv_bfloat16 g_qhi[PLANE_ELEMS], g_qlo[PLANE_ELEMS];
__device__ __nv_bfloat16 g_khi[PLANE_ELEMS], g_klo[PLANE_ELEMS];
__device__ __nv_bfloat16 g_vhi[PLANE_ELEMS], g_vlo[PLANE_ELEMS];
__device__ __nv_bfloat16 g_xhi[(size_t)BATCH * S_LEN * DIM], g_xlo[(size_t)BATCH * S_LEN * DIM];
__device__ __nv_bfloat16 g_ahi[(size_t)BATCH * S_LEN * DIM], g_alo[(size_t)BATCH * S_LEN * DIM];
__device__ __nv_bfloat16 g_wqhi[(size_t)(3 * DIM) * DIM], g_wqlo[(size_t)(3 * DIM) * DIM];
__device__ __nv_bfloat16 g_wohi[(size_t)DIM * DIM], g_wolo[(size_t)DIM * DIM];

// ---------------------------------------------------------------------------
// helpers
// ---------------------------------------------------------------------------
__device__ __forceinline__ uint32_t smem_to_u32(const void* p) {
    uint32_t a;
    asm("{ .reg .u64 t; cvta.to.shared.u64 t, %1; cvt.u32.u64 %0, t; }"
        : "=r"(a) : "l"(p));
    return a;
}

__device__ __forceinline__ void ldsm4(uint32_t* r, uint32_t addr) {
    asm volatile("ldmatrix.sync.aligned.m8n8.x4.shared.b16 {%0,%1,%2,%3}, [%4];"
                 : "=r"(r[0]), "=r"(r[1]), "=r"(r[2]), "=r"(r[3]) : "r"(addr));
}

__device__ __forceinline__ void ldsm4t(uint32_t* r, uint32_t addr) {
    asm volatile("ldmatrix.sync.aligned.m8n8.x4.trans.shared.b16 {%0,%1,%2,%3}, [%4];"
                 : "=r"(r[0]), "=r"(r[1]), "=r"(r[2]), "=r"(r[3]) : "r"(addr));
}

__device__ __forceinline__ void mma_bf16(float* d, const uint32_t* a, const uint32_t* b) {
    asm volatile(
        "mma.sync.aligned.m16n8k16.row.col.f32.bf16.bf16.f32 "
        "{%0,%1,%2,%3}, {%4,%5,%6,%7}, {%8,%9}, {%0,%1,%2,%3};"
        : "+f"(d[0]), "+f"(d[1]), "+f"(d[2]), "+f"(d[3])
        : "r"(a[0]), "r"(a[1]), "r"(a[2]), "r"(a[3]), "r"(b[0]), "r"(b[1]));
}

// pack (x0,x1) -> bf16x2 hi (low half = x0) and bf16x2 lo (residuals)
__device__ __forceinline__ void split_bf16x2(float x0, float x1,
                                             uint32_t& hi, uint32_t& lo) {
    asm("cvt.rn.bf16x2.f32 %0, %1, %2;" : "=r"(hi) : "f"(x1), "f"(x0));
    float h0 = __uint_as_float(hi << 16);
    float h1 = __uint_as_float(hi & 0xffff0000u);
    float r0 = x0 - h0;
    float r1 = x1 - h1;
    asm("cvt.rn.bf16x2.f32 %0, %1, %2;" : "=r"(lo) : "f"(r1), "f"(r0));
}

#define CP_ASYNC16(dst, src) \
    asm volatile("cp.async.cg.shared.global [%0], [%1], 16;" \
                 :: "r"(dst), "l"(src) : "memory")
#define CP_COMMIT() asm volatile("cp.async.commit_group;" ::: "memory")
#define CP_WAIT1()  asm volatile("cp.async.wait_group 1;" ::: "memory")
#define CP_WAIT2()  asm volatile("cp.async.wait_group 2;" ::: "memory")

// ---------------------------------------------------------------------------
// Elementwise split: fp32 -> bf16 hi/lo planes (float2 granular)
// ---------------------------------------------------------------------------
__global__ __launch_bounds__(256) void split_kernel(
    const float* __restrict__ in,
    __nv_bfloat16* __restrict__ hi, __nv_bfloat16* __restrict__ lo, size_t n2)
{
    size_t i = (size_t)blockIdx.x * blockDim.x + threadIdx.x;
    size_t stride = (size_t)gridDim.x * blockDim.x;
    for (; i < n2; i += stride) {
        float2 v = *(const float2*)(in + 2 * i);
        uint32_t h, l;
        split_bf16x2(v.x, v.y, h, l);
        *(uint32_t*)(hi + 2 * i) = h;
        *(uint32_t*)(lo + 2 * i) = l;
    }
}

// ---------------------------------------------------------------------------
// Transpose + split: fp32 in[R][C] -> bf16 hi/lo out[C][R]
// ---------------------------------------------------------------------------
__global__ __launch_bounds__(256) void transpose_split2_kernel(
    const float* __restrict__ in,
    __nv_bfloat16* __restrict__ hi, __nv_bfloat16* __restrict__ lo, int R, int C)
{
    __shared__ float t[32][33];
    int bx = blockIdx.x * 32;
    int by = blockIdx.y * 32;
    int x = threadIdx.x, y = threadIdx.y;   // 32 x 8
#pragma unroll
    for (int j = 0; j < 32; j += 8)
        t[y + j][x] = in[(size_t)(by + y + j) * C + bx + x];
    __syncthreads();
#pragma unroll
    for (int jj = 0; jj < 2; jj++) {
        int cp = y + 8 * jj;                 // 0..15 col pair index
        uint32_t h, l;
        split_bf16x2(t[cp * 2][x], t[cp * 2 + 1][x], h, l);
        size_t o = (size_t)(bx + x) * R + by + cp * 2;
        *(uint32_t*)(hi + o) = h;
        *(uint32_t*)(lo + o) = l;
    }
}

// ---------------------------------------------------------------------------
// Pure-bf16 plane GEMM: C = A @ B^T (+bias), A/B pre-split hi/lo planes [*,K]
// 128x128 tile, BK=32, 256 threads, 3-stage cp.async pipeline.
// Sweep-ordered mma: 16 independent accumulators between same-acc reuse.
// ---------------------------------------------------------------------------
#define GSTRIDE      80
#define GSTAGE_BYTES 40960
#define GSMEM_BYTES  (3 * GSTAGE_BYTES)

#define GEMM_PL_BODY                                                          \
    extern __shared__ __align__(1024) char smem[];                            \
    const uint32_t sb = smem_to_u32(smem);                                    \
    const int tid = threadIdx.x;                                              \
    const int wid = tid >> 5, lid = tid & 31;                                 \
    const int wm = wid >> 1;                                                  \
    const int wn = wid & 1;                                                   \
    const int m0 = blockIdx.y * 128;                                          \
    const int n0 = blockIdx.x * 128;                                          \
    const uint32_t aBase = (uint32_t)((wm * 32 + (lid & 15)) * GSTRIDE + (lid >> 4) * 16); \
    const uint32_t bBase = (uint32_t)((wn * 64 + ((lid >> 1) & 8) + (lid & 7)) * GSTRIDE \
                                      + ((lid & 8) << 1));                    \
    const int lrow = tid >> 1;                                                \
    const int lc0 = (tid & 1) * 2;                                            \
    float acc[2][8][4];                                                       \
    _Pragma("unroll")                                                         \
    for (int mf = 0; mf < 2; mf++)                                            \
        _Pragma("unroll")                                                     \
        for (int nf = 0; nf < 8; nf++)                                        \
            _Pragma("unroll")                                                 \
            for (int q = 0; q < 4; q++) acc[mf][nf][q] = 0.f;                 \
    const int niter = K >> 5;                                                 \
    auto issue = [&](int i, int s) {                                          \
        const int k0 = i << 5;                                                \
        const uint32_t base = sb + s * GSTAGE_BYTES;                          \
        const uint32_t so = (uint32_t)(lrow * GSTRIDE + lc0 * 16);            \
        const size_t ga = (size_t)(m0 + lrow) * K + k0 + lc0 * 8;             \
        const size_t gb = (size_t)(n0 + lrow) * K + k0 + lc0 * 8;             \
        CP_ASYNC16(base + so,              (const char*)(Ahi + ga));          \
        CP_ASYNC16(base + so + 16,         (const char*)(Ahi + ga + 8));      \
        CP_ASYNC16(base + 10240 + so,      (const char*)(Alo + ga));          \
        CP_ASYNC16(base + 10240 + so + 16, (const char*)(Alo + ga + 8));      \
        CP_ASYNC16(base + 20480 + so,      (const char*)(Bhi + gb));          \
        CP_ASYNC16(base + 20480 + so + 16, (const char*)(Bhi + gb + 8));      \
        CP_ASYNC16(base + 30720 + so,      (const char*)(Blo + gb));          \
        CP_ASYNC16(base + 30720 + so + 16, (const char*)(Blo + gb + 8));      \
    };                                                                        \
    issue(0, 0); CP_COMMIT();                                                 \
    if (niter > 1) { issue(1, 1); CP_COMMIT(); }                              \
    for (int i = 0; i < niter; i++) {                                         \
        const int s = i % 3;                                                  \
        if (i + 2 < niter) issue(i + 2, (i + 2) % 3);                         \
        CP_COMMIT();                                                          \
        CP_WAIT2();                                                          \
        __syncthreads();                                                      \
        const uint32_t sA = sb + s * GSTAGE_BYTES;                            \
        _Pragma("unroll")                                                     \
        for (int kstep = 0; kstep < 2; kstep++) {                             \
            const uint32_t koff = kstep * 32;                                 \
            uint32_t ahi[2][4], alo[2][4];                                    \
            ldsm4(ahi[0], sA + aBase + koff);                                 \
            ldsm4(ahi[1], sA + aBase + 16 * GSTRIDE + koff);                  \
            ldsm4(alo[0], sA + 10240 + aBase + koff);                         \
            ldsm4(alo[1], sA + 10240 + aBase + 16 * GSTRIDE + koff);          \
            uint32_t bhi[8][2], blo[8][2];                                    \
            _Pragma("unroll")                                                 \
            for (int t2 = 0; t2 < 4; t2++) {                                  \
                uint32_t r[4];                                                \
                ldsm4(r, sA + 20480 + bBase + t2 * 16 * GSTRIDE + koff);      \
                bhi[2 * t2][0] = r[0]; bhi[2 * t2][1] = r[1];                 \
                bhi[2 * t2 + 1][0] = r[2]; bhi[2 * t2 + 1][1] = r[3];         \
                ldsm4(r, sA + 30720 + bBase + t2 * 16 * GSTRIDE + koff);      \
                blo[2 * t2][0] = r[0]; blo[2 * t2][1] = r[1];                 \
                blo[2 * t2 + 1][0] = r[2]; blo[2 * t2 + 1][1] = r[3];         \
            }                                                                 \
            /* sweep 1: hi*hi over all 16 independent accumulators */         \
            _Pragma("unroll")                                                 \
            for (int mf = 0; mf < 2; mf++)                                    \
                _Pragma("unroll")                                             \
                for (int nf = 0; nf < 8; nf++)                                \
                    mma_bf16(acc[mf][nf], ahi[mf], bhi[nf]);                  \
            /* sweep 2: hi*lo */                                              \
            _Pragma("unroll")                                                 \
            for (int mf = 0; mf < 2; mf++)                                    \
                _Pragma("unroll")                                             \
                for (int nf = 0; nf < 8; nf++)                                \
                    mma_bf16(acc[mf][nf], ahi[mf], blo[nf]);                  \
            /* sweep 3: lo*hi */                                              \
            _Pragma("unroll")                                                 \
            for (int mf = 0; mf < 2; mf++)                                    \
                _Pragma("unroll")                                             \
                for (int nf = 0; nf < 8; nf++)                                \
                    mma_bf16(acc[mf][nf], alo[mf], bhi[nf]);                  \
        }                                                                     \
        __syncthreads();                                                      \
    }

// fp32 output GEMM (output projection)
__global__ __launch_bounds__(256, 1) void gemm_pl_out_kernel(
    const __nv_bfloat16* __restrict__ Ahi, const __nv_bfloat16* __restrict__ Alo,
    const __nv_bfloat16* __restrict__ Bhi, const __nv_bfloat16* __restrict__ Blo,
    const float* __restrict__ bias, float* __restrict__ C, int N, int K)
{
    GEMM_PL_BODY
    const int erow = m0 + wm * 32 + (lid >> 2);
    const int ecol0 = n0 + wn * 64 + (lid & 3) * 2;
#pragma unroll
    for (int mf = 0; mf < 2; mf++) {
#pragma unroll
        for (int nf = 0; nf < 8; nf++) {
            int col = ecol0 + nf * 8;
            float2 bz = *(const float2*)(bias + col);
            float2 v0, v1;
            v0.x = acc[mf][nf][0] + bz.x; v0.y = acc[mf][nf][1] + bz.y;
            v1.x = acc[mf][nf][2] + bz.x; v1.y = acc[mf][nf][3] + bz.y;
            size_t r0 = (size_t)(erow + mf * 16) * N + col;
            *(float2*)(C + r0) = v0;
            *(float2*)(C + r0 + 8 * N) = v1;
        }
    }
}

// QKV GEMM: writes bf16 hi/lo planes (Q pre-scaled)
__global__ __launch_bounds__(256, 1) void gemm_pl_qkv_kernel(
    const __nv_bfloat16* __restrict__ Ahi, const __nv_bfloat16* __restrict__ Alo,
    const __nv_bfloat16* __restrict__ Bhi, const __nv_bfloat16* __restrict__ Blo,
    const float* __restrict__ bias,
    __nv_bfloat16* __restrict__ qhi, __nv_bfloat16* __restrict__ qlo,
    __nv_bfloat16* __restrict__ khi, __nv_bfloat16* __restrict__ klo,
    __nv_bfloat16* __restrict__ vhi, __nv_bfloat16* __restrict__ vlo,
    int N, int K)
{
    GEMM_PL_BODY
    const int t = n0 >> 11;                 // 0=Q 1=K 2=V
    const int head = (n0 >> 7) & (HEADS - 1);
    __nv_bfloat16 *phi, *plo;
    if (t == 0)      { phi = qhi; plo = qlo; }
    else if (t == 1) { phi = khi; plo = klo; }
    else             { phi = vhi; plo = vlo; }
    const float sc = (t == 0) ? 0.08838834764831845f : 1.0f;
    const int erow = m0 + wm * 32 + (lid >> 2);
    const int lcol0 = wn * 64 + (lid & 3) * 2;
#pragma unroll
    for (int mf = 0; mf < 2; mf++) {
        int tok0 = erow + mf * 16;
        int b = tok0 >> 11;
        int s0 = tok0 & 2047;
        size_t pb = ((size_t)(b * HEADS + head) * S_LEN) * HD;
#pragma unroll
        for (int nf = 0; nf < 8; nf++) {
            int lc = lcol0 + nf * 8;
            float2 bz = *(const float2*)(bias + n0 + lc);
            float v0 = (acc[mf][nf][0] + bz.x) * sc;
            float v1 = (acc[mf][nf][1] + bz.y) * sc;
            float v2 = (acc[mf][nf][2] + bz.x) * sc;
            float v3 = (acc[mf][nf][3] + bz.y) * sc;
            uint32_t h, l;
            split_bf16x2(v0, v1, h, l);
            size_t p0 = pb + (size_t)s0 * HD + lc;
            *(uint32_t*)(phi + p0) = h;
            *(uint32_t*)(plo + p0) = l;
            split_bf16x2(v2, v3, h, l);
            size_t p1 = pb + (size_t)(s0 + 8) * HD + lc;
            *(uint32_t*)(phi + p1) = h;
            *(uint32_t*)(plo + p1) = l;
        }
    }
}

// ---------------------------------------------------------------------------
// Tensor-core flash attention (bf16 3-pass split) with segment+causal mask.
// grid (32, HEADS, BATCH), 256 threads = 8 warps (4 m-slabs x 2 key-slabs).
// Output: bf16 hi/lo planes of the normalized attention output.
// ---------------------------------------------------------------------------
#define AQ_STRIDE 272                 // smem bytes per row (136 halves)
#define SQHI 0
#define SQLO 17408
#define SSTAGE0 34816
#define SSTAGE_BYTES 69632            // Khi,Klo,Vhi,Vlo
#define SKHI 0
#define SKLO 17408
#define SVHI 34816
#define SVLO 52224
#define SKID  174080                  // + stage*256
#define SPMAX 174592
#define SLSUM 175104
#define ATTN_SMEM 175616

__global__ __launch_bounds__(256, 1) void attn_mma_kernel(
    const int* __restrict__ ids,
    __nv_bfloat16* __restrict__ ohi, __nv_bfloat16* __restrict__ olo,
    const __nv_bfloat16* __restrict__ qhi, const __nv_bfloat16* __restrict__ qlo,
    const __nv_bfloat16* __restrict__ khi, const __nv_bfloat16* __restrict__ klo,
    const __nv_bfloat16* __restrict__ vhi, const __nv_bfloat16* __restrict__ vlo)
{
    extern __shared__ __align__(1024) char smem[];
    const uint32_t sb = smem_to_u32(smem);
    const int tid = threadIdx.x;
    const int lane = tid & 31, wid = tid >> 5;
    const int wm = wid >> 1, wn = wid & 1;
    const int b = blockIdx.z, h = blockIdx.y;
    const int qt = gridDim.x - 1 - blockIdx.x;       // big tiles first
    const int q0 = qt * 64;
    const size_t pbase = (size_t)(b * HEADS + h) * S_LEN * HD;
    const int* bids = ids + b * S_LEN;

    const int lr = lane >> 2;
    const int row0 = wm * 16 + lr, row1 = row0 + 8;
    const int qrow0 = q0 + row0, qrow1 = q0 + row1;
    const int qidv0 = bids[qrow0], qidv1 = bids[qrow1];
    const int qid_min = bids[q0];

    float* pmax = (float*)(smem + SPMAX);
    float* lsum = (float*)(smem + SLSUM);

    auto issue_tile = [&](int kb, int s) {
        const int k0 = kb * 64;
        const uint32_t stg = sb + SSTAGE0 + s * SSTAGE_BYTES;
#pragma unroll
        for (int j = 0; j < 4; j++) {
            int q = tid + 256 * j;
            int key = q >> 4, c16 = q & 15;
            uint32_t soff = (uint32_t)(key * AQ_STRIDE + c16 * 16);
            size_t goff = pbase + (size_t)(k0 + key) * HD + c16 * 8;
            CP_ASYNC16(stg + SKHI + soff, (const char*)(khi + goff));
            CP_ASYNC16(stg + SKLO + soff, (const char*)(klo + goff));
            CP_ASYNC16(stg + SVHI + soff, (const char*)(vhi + goff));
            CP_ASYNC16(stg + SVLO + soff, (const char*)(vlo + goff));
        }
        if (tid < 16)
            CP_ASYNC16(sb + SKID + s * 256 + tid * 16,
                       (const char*)(bids + k0 + tid * 4));
    };

    // ---- prologue: Q planes + tile 0 in cp.async group 0 ----
#pragma unroll
    for (int j = 0; j < 4; j++) {
        int q = tid + 256 * j;
        int key = q >> 4, c16 = q & 15;
        uint32_t soff = (uint32_t)(key * AQ_STRIDE + c16 * 16);
        size_t goff = pbase + (size_t)(q0 + key) * HD + c16 * 8;
        CP_ASYNC16(sb + SQHI + soff, (const char*)(qhi + goff));
        CP_ASYNC16(sb + SQLO + soff, (const char*)(qlo + goff));
    }
    issue_tile(0, 0);
    CP_COMMIT();

    float O[16][4];
#pragma unroll
    for (int nb = 0; nb < 16; nb++)
#pragma unroll
        for (int q = 0; q < 4; q++) O[nb][q] = 0.f;
    float m0r = -1e30f, m1r = -1e30f, l0r = 0.f, l1r = 0.f;

    const uint32_t qoffA = (uint32_t)((wm * 16 + (lane & 15)) * AQ_STRIDE + (lane >> 4) * 16);
    const uint32_t kBoff = (uint32_t)((wn * 32 + ((lane >> 1) & 8) + (lane & 7)) * AQ_STRIDE
                                      + ((lane & 8) << 1));
    const uint32_t vBoff = (uint32_t)((wn * 32 + ((lane >> 3) & 1) * 8 + (lane & 7)) * AQ_STRIDE
                                      + ((lane >> 4) & 1) * 16);

    const int nkb = qt;
    for (int kb = 0; kb <= nkb; kb++) {
        const int s = kb & 1;
        if (kb + 1 <= nkb) {
            bool skip_next = (bids[(kb + 1) * 64 + 63] < qid_min);
            if (!skip_next) issue_tile(kb + 1, s ^ 1);
        }
        CP_COMMIT();
        CP_WAIT1();
        __syncthreads();

        bool skip_cur = (bids[kb * 64 + 63] < qid_min);
        if (!skip_cur) {
            const uint32_t stg = sb + SSTAGE0 + s * SSTAGE_BYTES;
            const int k0 = kb * 64;

            // ---- S = Q K^T (3-pass split, sweep-ordered) ----
            float S[4][4];
#pragma unroll
            for (int nf = 0; nf < 4; nf++)
#pragma unroll
                for (int c = 0; c < 4; c++) S[nf][c] = 0.f;
#pragma unroll
            for (int ks = 0; ks < 8; ks++) {
                uint32_t ah[4], al[4];
                ldsm4(ah, sb + SQHI + qoffA + ks * 32);
                ldsm4(al, sb + SQLO + qoffA + ks * 32);
                uint32_t bh0[4], bh1[4], bl0[4], bl1[4];
                ldsm4(bh0, stg + SKHI + kBoff + ks * 32);
                ldsm4(bh1, stg + SKHI + kBoff + 16 * AQ_STRIDE + ks * 32);
                ldsm4(bl0, stg + SKLO + kBoff + ks * 32);
                ldsm4(bl1, stg + SKLO + kBoff + 16 * AQ_STRIDE + ks * 32);
                // sweep hi*hi
                mma_bf16(S[0], ah, bh0 + 0); mma_bf16(S[1], ah, bh0 + 2);
                mma_bf16(S[2], ah, bh1 + 0); mma_bf16(S[3], ah, bh1 + 2);
                // sweep hi*lo
                mma_bf16(S[0], ah, bl0 + 0); mma_bf16(S[1], ah, bl0 + 2);
                mma_bf16(S[2], ah, bl1 + 0); mma_bf16(S[3], ah, bl1 + 2);
                // sweep lo*hi
                mma_bf16(S[0], al, bh0 + 0); mma_bf16(S[1], al, bh0 + 2);
                mma_bf16(S[2], al, bh1 + 0); mma_bf16(S[3], al, bh1 + 2);
            }

            // ---- mask + tile row max ----
            const uint32_t kidb = sb + SKID + s * 256;
            float mt0 = -1e30f, mt1 = -1e30f;
#pragma unroll
            for (int nf = 0; nf < 4; nf++) {
                int lc = wn * 32 + nf * 8 + 2 * (lane & 3);
                int kv0, kv1;
                asm volatile("ld.shared.v2.u32 {%0,%1}, [%2];"
                             : "=r"(kv0), "=r"(kv1) : "r"(kidb + lc * 4));
                int key = k0 + lc;
                if (key     > qrow0 || kv0 != qidv0) S[nf][0] = -1e30f;
                if (key + 1 > qrow0 || kv1 != qidv0) S[nf][1] = -1e30f;
                if (key     > qrow1 || kv0 != qidv1) S[nf][2] = -1e30f;
                if (key + 1 > qrow1 || kv1 != qidv1) S[nf][3] = -1e30f;
                mt0 = fmaxf(mt0, fmaxf(S[nf][0], S[nf][1]));
                mt1 = fmaxf(mt1, fmaxf(S[nf][2], S[nf][3]));
            }
            mt0 = fmaxf(mt0, __shfl_xor_sync(0xffffffffu, mt0, 1));
            mt0 = fmaxf(mt0, __shfl_xor_sync(0xffffffffu, mt0, 2));
            mt1 = fmaxf(mt1, __shfl_xor_sync(0xffffffffu, mt1, 1));
            mt1 = fmaxf(mt1, __shfl_xor_sync(0xffffffffu, mt1, 2));
            if ((lane & 3) == 0) {
                pmax[wn * 64 + row0] = mt0;
                pmax[wn * 64 + row1] = mt1;
            }
            __syncthreads();

            float mn0 = fmaxf(m0r, fmaxf(pmax[row0], pmax[64 + row0]));
            float mn1 = fmaxf(m1r, fmaxf(pmax[row1], pmax[64 + row1]));
            float f0 = __expf(m0r - mn0), f1 = __expf(m1r - mn1);
            m0r = mn0; m1r = mn1;

            float rs0 = 0.f, rs1 = 0.f;
#pragma unroll
            for (int nf = 0; nf < 4; nf++) {
                float p0 = (S[nf][0] < -1e29f) ? 0.f : __expf(S[nf][0] - mn0);
                float p1 = (S[nf][1] < -1e29f) ? 0.f : __expf(S[nf][1] - mn0);
                float p2 = (S[nf][2] < -1e29f) ? 0.f : __expf(S[nf][2] - mn1);
                float p3 = (S[nf][3] < -1e29f) ? 0.f : __expf(S[nf][3] - mn1);
                S[nf][0] = p0; S[nf][1] = p1; S[nf][2] = p2; S[nf][3] = p3;
                rs0 += p0 + p1; rs1 += p2 + p3;
            }
            rs0 += __shfl_xor_sync(0xffffffffu, rs0, 1);
            rs0 += __shfl_xor_sync(0xffffffffu, rs0, 2);
            rs1 += __shfl_xor_sync(0xffffffffu, rs1, 1);
            rs1 += __shfl_xor_sync(0xffffffffu, rs1, 2);
            l0r = l0r * f0 + rs0;
            l1r = l1r * f1 + rs1;

            // rescale O
#pragma unroll
            for (int nb = 0; nb < 16; nb++) {
                O[nb][0] *= f0; O[nb][1] *= f0;
                O[nb][2] *= f1; O[nb][3] *= f1;
            }

            // ---- O += P V (split P and V, 3-pass, nb-pair sweeps) ----
#pragma unroll
            for (int ks2 = 0; ks2 < 2; ks2++) {
                uint32_t ah[4], al[4];
                split_bf16x2(S[2 * ks2][0],     S[2 * ks2][1],     ah[0], al[0]);
                split_bf16x2(S[2 * ks2][2],     S[2 * ks2][3],     ah[1], al[1]);
                split_bf16x2(S[2 * ks2 + 1][0], S[2 * ks2 + 1][1], ah[2], al[2]);
                split_bf16x2(S[2 * ks2 + 1][2], S[2 * ks2 + 1][3], ah[3], al[3]);
                uint32_t ro = vBoff + ks2 * 16 * AQ_STRIDE;
#pragma unroll
                for (int np = 0; np < 4; np++) {
                    uint32_t bh0[4], bh1[4], bl0[4], bl1[4];
                    ldsm4t(bh0, stg + SVHI + ro + (2 * np) * 32);
                    ldsm4t(bh1, stg + SVHI + ro + (2 * np + 1) * 32);
                    ldsm4t(bl0, stg + SVLO + ro + (2 * np) * 32);
                    ldsm4t(bl1, stg + SVLO + ro + (2 * np + 1) * 32);
                    int o0 = 4 * np;
                    // sweep hi
                    mma_bf16(O[o0 + 0], ah, bh0 + 0); mma_bf16(O[o0 + 1], ah, bh0 + 2);
                    mma_bf16(O[o0 + 2], ah, bh1 + 0); mma_bf16(O[o0 + 3], ah, bh1 + 2);
                    // sweep P*Vlo
                    mma_bf16(O[o0 + 0], ah, bl0 + 0); mma_bf16(O[o0 + 1], ah, bl0 + 2);
                    mma_bf16(O[o0 + 2], ah, bl1 + 0); mma_bf16(O[o0 + 3], ah, bl1 + 2);
                    // sweep Plo*Vhi
                    mma_bf16(O[o0 + 0], al, bh0 + 0); mma_bf16(O[o0 + 1], al, bh0 + 2);
                    mma_bf16(O[o0 + 2], al, bh1 + 0); mma_bf16(O[o0 + 3], al, bh1 + 2);
                }
            }
        }
        __syncthreads();
    }

    // ---- epilogue: combine l across warp pairs, then O, then write planes ----
    if ((lane & 3) == 0) {
        lsum[wn * 64 + row0] = l0r;
        lsum[wn * 64 + row1] = l1r;
    }
    __syncthreads();
    float inv0 = 1.f / (lsum[row0] + lsum[64 + row0]);
    float inv1 = 1.f / (lsum[row1] + lsum[64 + row1]);

    if (wn == 1) {
#pragma unroll
        for (int nb = 0; nb < 16; nb++) {
            uint32_t off = (uint32_t)(wm * 8192 + lr * 512 + (nb * 8 + 2 * (lane & 3)) * 4);
            *(float2*)(smem + off) = make_float2(O[nb][0], O[nb][1]);
            *(float2*)(smem + off + 8 * 512) = make_float2(O[nb][2], O[nb][3]);
        }
    }
    __syncthreads();
    if (wn == 0) {
        const size_t g0 = ((size_t)b * S_LEN + qrow0) * DIM + h * HD;
        const size_t g1 = ((size_t)b * S_LEN + qrow1) * DIM + h * HD;
#pragma unroll
        for (int nb = 0; nb < 16; nb++) {
            int col = nb * 8 + 2 * (lane & 3);
            uint32_t off = (uint32_t)(wm * 8192 + lr * 512 + col * 4);
            float2 o0 = *(float2*)(smem + off);
            float2 o1 = *(float2*)(smem + off + 8 * 512);
            uint32_t hh, ll;
            split_bf16x2((O[nb][0] + o0.x) * inv0, (O[nb][1] + o0.y) * inv0, hh, ll);
            *(uint32_t*)(ohi + g0 + col) = hh;
            *(uint32_t*)(olo + g0 + col) = ll;
            split_bf16x2((O[nb][2] + o1.x) * inv1, (O[nb][3] + o1.y) * inv1, hh, ll);
            *(uint32_t*)(ohi + g1 + col) = hh;
            *(uint32_t*)(olo + g1 + col) = ll;
        }
    }
}

// ---------------------------------------------------------------------------
extern "C" void kernel_launch(void* const* d_in, const int* in_sizes, int n_in,
                              void* d_out, int out_size)
{
    const float* x    = (const float*)d_in[0];   // [4,2048,2048]
    const int*   ids  = (const int*)d_in[1];     // [4,2048]
    const float* Wqkv = (const float*)d_in[2];   // [2048,6144]
    const float* bqkv = (const float*)d_in[3];   // [6144]
    const float* Wo   = (const float*)d_in[4];   // [2048,2048]
    const float* bo   = (const float*)d_in[5];   // [2048]
    float* out = (float*)d_out;

    __nv_bfloat16 *qhi, *qlo, *khi, *klo, *vhi, *vlo;
    __nv_bfloat16 *xhi, *xlo, *ahi, *alo, *wqhi, *wqlo, *wohi, *wolo;
    cudaGetSymbolAddress((void**)&qhi, g_qhi);
    cudaGetSymbolAddress((void**)&qlo, g_qlo);
    cudaGetSymbolAddress((void**)&khi, g_khi);
    cudaGetSymbolAddress((void**)&klo, g_klo);
    cudaGetSymbolAddress((void**)&vhi, g_vhi);
    cudaGetSymbolAddress((void**)&vlo, g_vlo);
    cudaGetSymbolAddress((void**)&xhi, g_xhi);
    cudaGetSymbolAddress((void**)&xlo, g_xlo);
    cudaGetSymbolAddress((void**)&ahi, g_ahi);
    cudaGetSymbolAddress((void**)&alo, g_alo);
    cudaGetSymbolAddress((void**)&wqhi, g_wqhi);
    cudaGetSymbolAddress((void**)&wqlo, g_wqlo);
    cudaGetSymbolAddress((void**)&wohi, g_wohi);
    cudaGetSymbolAddress((void**)&wolo, g_wolo);

    cudaFuncSetAttribute(gemm_pl_out_kernel,
                         cudaFuncAttributeMaxDynamicSharedMemorySize, GSMEM_BYTES);
    cudaFuncSetAttribute(gemm_pl_qkv_kernel,
                         cudaFuncAttributeMaxDynamicSharedMemorySize, GSMEM_BYTES);
    cudaFuncSetAttribute(attn_mma_kernel,
                         cudaFuncAttributeMaxDynamicSharedMemorySize, ATTN_SMEM);

    const int M = BATCH * S_LEN;   // 8192

    // 0) pre-split x and weights (one-shot)
    split_kernel<<<1184, 256>>>(x, xhi, xlo, (size_t)M * DIM / 2);
    {
        dim3 blk(32, 8);
        transpose_split2_kernel<<<dim3(3 * DIM / 32, DIM / 32), blk>>>(Wqkv, wqhi, wqlo, DIM, 3 * DIM);
        transpose_split2_kernel<<<dim3(DIM / 32, DIM / 32), blk>>>(Wo, wohi, wolo, DIM, DIM);
    }
    // 1) QKV = x @ Wqkv + bqkv -> bf16 hi/lo planes (Q pre-scaled)
    {
        dim3 grid(3 * DIM / 128, M / 128);
        gemm_pl_qkv_kernel<<<grid, 256, GSMEM_BYTES>>>(
            xhi, xlo, wqhi, wqlo, bqkv, qhi, qlo, khi, klo, vhi, vlo, 3 * DIM, DIM);
    }
    // 2) flash attention -> bf16 hi/lo planes
    {
        dim3 grid(S_LEN / 64, HEADS, BATCH);
        attn_mma_kernel<<<grid, 256, ATTN_SMEM>>>(
            ids, ahi, alo, qhi, qlo, khi, klo, vhi, vlo);
    }
    // 3) out = attn @ Wo + bo  [8192, 2048] fp32
    {
        dim3 grid(DIM / 128, M / 128);
        gemm_pl_out_kernel<<<grid, 256, GSMEM_BYTES>>>(
            ahi, alo, wohi, wolo, bo, out, DIM, DIM);
    }
}

// round 8
// speedup vs baseline: 1.7668x; 1.7654x over previous
#include <cuda_runtime.h>
#include <cuda_fp16.h>
#include <cstdint>
#include <cstddef>

#define S_LEN 2048
#define DIM   2048
#define HEADS 16
#define HD    128
#define BATCH 4

// Scratch (allocation-free rule: __device__ globals)
#define PLANE_ELEMS ((size_t)BATCH * HEADS * S_LEN * HD)
__device__ __half g_qhi[PLANE_ELEMS], g_qlo[PLANE_ELEMS];
__device__ __half g_khi[PLANE_ELEMS];
__device__ __half g_vhi[PLANE_ELEMS];
__device__ __half g_xhi[(size_t)BATCH * S_LEN * DIM], g_xlo[(size_t)BATCH * S_LEN * DIM];
__device__ __half g_ahi[(size_t)BATCH * S_LEN * DIM], g_alo[(size_t)BATCH * S_LEN * DIM];
__device__ __half g_wqh[(size_t)(3 * DIM) * DIM];
__device__ __half g_woh[(size_t)DIM * DIM];

// ---------------------------------------------------------------------------
// helpers
// ---------------------------------------------------------------------------
__device__ __forceinline__ uint32_t smem_to_u32(const void* p) {
    uint32_t a;
    asm("{ .reg .u64 t; cvta.to.shared.u64 t, %1; cvt.u32.u64 %0, t; }"
        : "=r"(a) : "l"(p));
    return a;
}

__device__ __forceinline__ void ldsm4(uint32_t* r, uint32_t addr) {
    asm volatile("ldmatrix.sync.aligned.m8n8.x4.shared.b16 {%0,%1,%2,%3}, [%4];"
                 : "=r"(r[0]), "=r"(r[1]), "=r"(r[2]), "=r"(r[3]) : "r"(addr));
}

__device__ __forceinline__ void ldsm4t(uint32_t* r, uint32_t addr) {
    asm volatile("ldmatrix.sync.aligned.m8n8.x4.trans.shared.b16 {%0,%1,%2,%3}, [%4];"
                 : "=r"(r[0]), "=r"(r[1]), "=r"(r[2]), "=r"(r[3]) : "r"(addr));
}

__device__ __forceinline__ void mma_f16(float* d, const uint32_t* a, const uint32_t* b) {
    asm volatile(
        "mma.sync.aligned.m16n8k16.row.col.f32.f16.f16.f32 "
        "{%0,%1,%2,%3}, {%4,%5,%6,%7}, {%8,%9}, {%0,%1,%2,%3};"
        : "+f"(d[0]), "+f"(d[1]), "+f"(d[2]), "+f"(d[3])
        : "r"(a[0]), "r"(a[1]), "r"(a[2]), "r"(a[3]), "r"(b[0]), "r"(b[1]));
}

// pack (x0,x1) -> fp16x2 (low half = x0)
__device__ __forceinline__ uint32_t packh2(float x0, float x1) {
    __half2 h = __floats2half2_rn(x0, x1);
    return *(uint32_t*)&h;
}

// x -> hi + lo, both fp16 (hi = RN(x), lo = RN(x - hi)); pair-packed
__device__ __forceinline__ void split_f16x2(float x0, float x1,
                                            uint32_t& hi, uint32_t& lo) {
    __half2 h = __floats2half2_rn(x0, x1);
    hi = *(uint32_t*)&h;
    float h0 = __low2float(h), h1 = __high2float(h);
    __half2 l = __floats2half2_rn(x0 - h0, x1 - h1);
    lo = *(uint32_t*)&l;
}

#define CP_ASYNC16(dst, src) \
    asm volatile("cp.async.cg.shared.global [%0], [%1], 16;" \
                 :: "r"(dst), "l"(src) : "memory")
#define CP_COMMIT() asm volatile("cp.async.commit_group;" ::: "memory")
#define CP_WAIT1()  asm volatile("cp.async.wait_group 1;" ::: "memory")

// ---------------------------------------------------------------------------
// Elementwise split: fp32 -> fp16 hi/lo planes
// ---------------------------------------------------------------------------
__global__ __launch_bounds__(256) void split_kernel(
    const float* __restrict__ in,
    __half* __restrict__ hi, __half* __restrict__ lo, size_t n2)
{
    size_t i = (size_t)blockIdx.x * blockDim.x + threadIdx.x;
    size_t stride = (size_t)gridDim.x * blockDim.x;
    for (; i < n2; i += stride) {
        float2 v = *(const float2*)(in + 2 * i);
        uint32_t h, l;
        split_f16x2(v.x, v.y, h, l);
        *(uint32_t*)(hi + 2 * i) = h;
        *(uint32_t*)(lo + 2 * i) = l;
    }
}

// ---------------------------------------------------------------------------
// Transpose + round: fp32 in[R][C] -> fp16 out[C][R]
// ---------------------------------------------------------------------------
__global__ __launch_bounds__(256) void transpose_round_kernel(
    const float* __restrict__ in, __half* __restrict__ out, int R, int C)
{
    __shared__ float t[32][33];
    int bx = blockIdx.x * 32;
    int by = blockIdx.y * 32;
    int x = threadIdx.x, y = threadIdx.y;   // 32 x 8
#pragma unroll
    for (int j = 0; j < 32; j += 8)
        t[y + j][x] = in[(size_t)(by + y + j) * C + bx + x];
    __syncthreads();
#pragma unroll
    for (int jj = 0; jj < 2; jj++) {
        int cp = y + 8 * jj;                 // 0..15 col pair index
        uint32_t h = packh2(t[cp * 2][x], t[cp * 2 + 1][x]);
        size_t o = (size_t)(bx + x) * R + by + cp * 2;
        *(uint32_t*)(out + o) = h;
    }
}

// ---------------------------------------------------------------------------
// fp16 2-product GEMM: C = (Ahi+Alo) @ Bh^T (+bias); A 2-plane, B rounded.
// 128x128 tile, BK=32, 256 threads, 3-stage cp.async pipeline, 2 CTAs/SM.
// Stage layout (row stride 80B): Ahi@0  Alo@10240  Bh@20480  (30720 B/stage)
// ---------------------------------------------------------------------------
#define GSTRIDE      80
#define GSTAGE_BYTES 30720
#define GSMEM_BYTES  (3 * GSTAGE_BYTES)

#define GEMM_PL_BODY                                                          \
    extern __shared__ __align__(1024) char smem[];                            \
    const uint32_t sb = smem_to_u32(smem);                                    \
    const int tid = threadIdx.x;                                              \
    const int wid = tid >> 5, lid = tid & 31;                                 \
    const int wm = wid >> 1;                                                  \
    const int wn = wid & 1;                                                   \
    const int m0 = blockIdx.y * 128;                                          \
    const int n0 = blockIdx.x * 128;                                          \
    const uint32_t aBase = (uint32_t)((wm * 32 + (lid & 15)) * GSTRIDE + (lid >> 4) * 16); \
    const uint32_t bBase = (uint32_t)((wn * 64 + ((lid >> 1) & 8) + (lid & 7)) * GSTRIDE \
                                      + ((lid & 8) << 1));                    \
    const int lrow = tid >> 1;                                                \
    const int lc0 = (tid & 1) * 2;                                            \
    float acc[2][8][4];                                                       \
    _Pragma("unroll")                                                         \
    for (int mf = 0; mf < 2; mf++)                                            \
        _Pragma("unroll")                                                     \
        for (int nf = 0; nf < 8; nf++)                                        \
            _Pragma("unroll")                                                 \
            for (int q = 0; q < 4; q++) acc[mf][nf][q] = 0.f;                 \
    const int niter = K >> 5;                                                 \
    auto issue = [&](int i, int s) {                                          \
        const int k0 = i << 5;                                                \
        const uint32_t base = sb + s * GSTAGE_BYTES;                          \
        const uint32_t so = (uint32_t)(lrow * GSTRIDE + lc0 * 16);            \
        const size_t ga = (size_t)(m0 + lrow) * K + k0 + lc0 * 8;             \
        const size_t gb = (size_t)(n0 + lrow) * K + k0 + lc0 * 8;             \
        CP_ASYNC16(base + so,              (const char*)(Ahi + ga));          \
        CP_ASYNC16(base + so + 16,         (const char*)(Ahi + ga + 8));      \
        CP_ASYNC16(base + 10240 + so,      (const char*)(Alo + ga));          \
        CP_ASYNC16(base + 10240 + so + 16, (const char*)(Alo + ga + 8));      \
        CP_ASYNC16(base + 20480 + so,      (const char*)(Bh + gb));           \
        CP_ASYNC16(base + 20480 + so + 16, (const char*)(Bh + gb + 8));       \
    };                                                                        \
    issue(0, 0); CP_COMMIT();                                                 \
    if (niter > 1) { issue(1, 1); CP_COMMIT(); }                              \
    for (int i = 0; i < niter; i++) {                                         \
        const int s = i % 3;                                                  \
        CP_WAIT1();                                                           \
        __syncthreads();                                                      \
        if (i + 2 < niter) issue(i + 2, (i + 2) % 3);                         \
        CP_COMMIT();                                                          \
        const uint32_t sA = sb + s * GSTAGE_BYTES;                            \
        _Pragma("unroll")                                                     \
        for (int kstep = 0; kstep < 2; kstep++) {                             \
            const uint32_t koff = kstep * 32;                                 \
            uint32_t ahi[2][4], alo[2][4];                                    \
            ldsm4(ahi[0], sA + aBase + koff);                                 \
            ldsm4(ahi[1], sA + aBase + 16 * GSTRIDE + koff);                  \
            ldsm4(alo[0], sA + 10240 + aBase + koff);                         \
            ldsm4(alo[1], sA + 10240 + aBase + 16 * GSTRIDE + koff);          \
            uint32_t bh[8][2];                                                \
            _Pragma("unroll")                                                 \
            for (int t2 = 0; t2 < 4; t2++) {                                  \
                uint32_t r[4];                                                \
                ldsm4(r, sA + 20480 + bBase + t2 * 16 * GSTRIDE + koff);      \
                bh[2 * t2][0] = r[0]; bh[2 * t2][1] = r[1];                   \
                bh[2 * t2 + 1][0] = r[2]; bh[2 * t2 + 1][1] = r[3];           \
            }                                                                 \
            _Pragma("unroll")                                                 \
            for (int mf = 0; mf < 2; mf++)                                    \
                _Pragma("unroll")                                             \
                for (int nf = 0; nf < 8; nf++)                                \
                    mma_f16(acc[mf][nf], ahi[mf], bh[nf]);                    \
            _Pragma("unroll")                                                 \
            for (int mf = 0; mf < 2; mf++)                                    \
                _Pragma("unroll")                                             \
                for (int nf = 0; nf < 8; nf++)                                \
                    mma_f16(acc[mf][nf], alo[mf], bh[nf]);                    \
        }                                                                     \
        __syncthreads();                                                      \
    }

// fp32 output GEMM (output projection)
__global__ __launch_bounds__(256, 2) void gemm2_out_kernel(
    const __half* __restrict__ Ahi, const __half* __restrict__ Alo,
    const __half* __restrict__ Bh,
    const float* __restrict__ bias, float* __restrict__ C, int N, int K)
{
    GEMM_PL_BODY
    const int erow = m0 + wm * 32 + (lid >> 2);
    const int ecol0 = n0 + wn * 64 + (lid & 3) * 2;
#pragma unroll
    for (int mf = 0; mf < 2; mf++) {
#pragma unroll
        for (int nf = 0; nf < 8; nf++) {
            int col = ecol0 + nf * 8;
            float2 bz = *(const float2*)(bias + col);
            float2 v0, v1;
            v0.x = acc[mf][nf][0] + bz.x; v0.y = acc[mf][nf][1] + bz.y;
            v1.x = acc[mf][nf][2] + bz.x; v1.y = acc[mf][nf][3] + bz.y;
            size_t r0 = (size_t)(erow + mf * 16) * N + col;
            *(float2*)(C + r0) = v0;
            *(float2*)(C + r0 + 8 * N) = v1;
        }
    }
}

// QKV GEMM: Q -> fp16 2-plane (pre-scaled), K/V -> fp16 single plane
__global__ __launch_bounds__(256, 2) void gemm2_qkv_kernel(
    const __half* __restrict__ Ahi, const __half* __restrict__ Alo,
    const __half* __restrict__ Bh,
    const float* __restrict__ bias,
    __half* __restrict__ qhi, __half* __restrict__ qlo,
    __half* __restrict__ khi, __half* __restrict__ vhi,
    int N, int K)
{
    GEMM_PL_BODY
    const int t = n0 >> 11;                 // 0=Q 1=K 2=V
    const int head = (n0 >> 7) & (HEADS - 1);
    const int erow = m0 + wm * 32 + (lid >> 2);
    const int lcol0 = wn * 64 + (lid & 3) * 2;
#pragma unroll
    for (int mf = 0; mf < 2; mf++) {
        int tok0 = erow + mf * 16;
        int b = tok0 >> 11;
        int s0 = tok0 & 2047;
        size_t pb = ((size_t)(b * HEADS + head) * S_LEN) * HD;
#pragma unroll
        for (int nf = 0; nf < 8; nf++) {
            int lc = lcol0 + nf * 8;
            float2 bz = *(const float2*)(bias + n0 + lc);
            float v0 = acc[mf][nf][0] + bz.x;
            float v1 = acc[mf][nf][1] + bz.y;
            float v2 = acc[mf][nf][2] + bz.x;
            float v3 = acc[mf][nf][3] + bz.y;
            size_t p0 = pb + (size_t)s0 * HD + lc;
            size_t p1 = pb + (size_t)(s0 + 8) * HD + lc;
            if (t == 0) {
                const float sc = 0.08838834764831845f;
                uint32_t h, l;
                split_f16x2(v0 * sc, v1 * sc, h, l);
                *(uint32_t*)(qhi + p0) = h;
                *(uint32_t*)(qlo + p0) = l;
                split_f16x2(v2 * sc, v3 * sc, h, l);
                *(uint32_t*)(qhi + p1) = h;
                *(uint32_t*)(qlo + p1) = l;
            } else {
                __half* p = (t == 1) ? khi : vhi;
                *(uint32_t*)(p + p0) = packh2(v0, v1);
                *(uint32_t*)(p + p1) = packh2(v2, v3);
            }
        }
    }
}

// ---------------------------------------------------------------------------
// Tensor-core flash attention (fp16): S = (Qhi+Qlo)·K^T (2 products),
// O += RN16(P)·V (1 product). Segment+causal mask, segment skip.
// grid (32, HEADS, BATCH), 256 threads = 8 warps (4 m-slabs x 2 key-slabs).
// Output: fp16 hi/lo planes of the normalized attention output.
// ---------------------------------------------------------------------------
#define AQ_STRIDE 272                 // smem bytes per row (128 fp16 + pad)
#define SQHI 0
#define SQLO 17408
#define SSTAGE0 34816
#define SSTAGE_BYTES 34816            // Kh, Vh
#define SKH 0
#define SVH 17408
#define SKID  104448                  // + stage*256
#define SPMAX 104960
#define SLSUM 105472
#define ATTN_SMEM 105984

__global__ __launch_bounds__(256, 1) void attn_mma_kernel(
    const int* __restrict__ ids,
    __half* __restrict__ ohi, __half* __restrict__ olo,
    const __half* __restrict__ qhi, const __half* __restrict__ qlo,
    const __half* __restrict__ khi, const __half* __restrict__ vhi)
{
    extern __shared__ __align__(1024) char smem[];
    const uint32_t sb = smem_to_u32(smem);
    const int tid = threadIdx.x;
    const int lane = tid & 31, wid = tid >> 5;
    const int wm = wid >> 1, wn = wid & 1;
    const int b = blockIdx.z, h = blockIdx.y;
    const int qt = gridDim.x - 1 - blockIdx.x;       // big tiles first
    const int q0 = qt * 64;
    const size_t pbase = (size_t)(b * HEADS + h) * S_LEN * HD;
    const int* bids = ids + b * S_LEN;

    const int lr = lane >> 2;
    const int row0 = wm * 16 + lr, row1 = row0 + 8;
    const int qrow0 = q0 + row0, qrow1 = q0 + row1;
    const int qidv0 = bids[qrow0], qidv1 = bids[qrow1];
    const int qid_min = bids[q0];

    float* pmax = (float*)(smem + SPMAX);
    float* lsum = (float*)(smem + SLSUM);

    auto issue_tile = [&](int kb, int s) {
        const int k0 = kb * 64;
        const uint32_t stg = sb + SSTAGE0 + s * SSTAGE_BYTES;
#pragma unroll
        for (int j = 0; j < 4; j++) {
            int q = tid + 256 * j;
            int key = q >> 4, c16 = q & 15;
            uint32_t soff = (uint32_t)(key * AQ_STRIDE + c16 * 16);
            size_t goff = pbase + (size_t)(k0 + key) * HD + c16 * 8;
            CP_ASYNC16(stg + SKH + soff, (const char*)(khi + goff));
            CP_ASYNC16(stg + SVH + soff, (const char*)(vhi + goff));
        }
        if (tid < 16)
            CP_ASYNC16(sb + SKID + s * 256 + tid * 16,
                       (const char*)(bids + k0 + tid * 4));
    };

    // ---- prologue: Q planes + tile 0 in cp.async group 0 ----
#pragma unroll
    for (int j = 0; j < 4; j++) {
        int q = tid + 256 * j;
        int key = q >> 4, c16 = q & 15;
        uint32_t soff = (uint32_t)(key * AQ_STRIDE + c16 * 16);
        size_t goff = pbase + (size_t)(q0 + key) * HD + c16 * 8;
        CP_ASYNC16(sb + SQHI + soff, (const char*)(qhi + goff));
        CP_ASYNC16(sb + SQLO + soff, (const char*)(qlo + goff));
    }
    issue_tile(0, 0);
    CP_COMMIT();

    float O[16][4];
#pragma unroll
    for (int nb = 0; nb < 16; nb++)
#pragma unroll
        for (int q = 0; q < 4; q++) O[nb][q] = 0.f;
    float m0r = -1e30f, m1r = -1e30f, l0r = 0.f, l1r = 0.f;

    const uint32_t qoffA = (uint32_t)((wm * 16 + (lane & 15)) * AQ_STRIDE + (lane >> 4) * 16);
    const uint32_t kBoff = (uint32_t)((wn * 32 + ((lane >> 1) & 8) + (lane & 7)) * AQ_STRIDE
                                      + ((lane & 8) << 1));
    const uint32_t vBoff = (uint32_t)((wn * 32 + ((lane >> 3) & 1) * 8 + (lane & 7)) * AQ_STRIDE
                                      + ((lane >> 4) & 1) * 16);

    const int nkb = qt;
    for (int kb = 0; kb <= nkb; kb++) {
        const int s = kb & 1;
        if (kb + 1 <= nkb) {
            bool skip_next = (bids[(kb + 1) * 64 + 63] < qid_min);
            if (!skip_next) issue_tile(kb + 1, s ^ 1);
        }
        CP_COMMIT();
        CP_WAIT1();
        __syncthreads();

        bool skip_cur = (bids[kb * 64 + 63] < qid_min);
        if (!skip_cur) {
            const uint32_t stg = sb + SSTAGE0 + s * SSTAGE_BYTES;
            const int k0 = kb * 64;

            // ---- S = (Qhi+Qlo)·K^T, 2 products, sweep-ordered ----
            float S[4][4];
#pragma unroll
            for (int nf = 0; nf < 4; nf++)
#pragma unroll
                for (int c = 0; c < 4; c++) S[nf][c] = 0.f;
#pragma unroll
            for (int ks = 0; ks < 8; ks++) {
                uint32_t ah[4], al[4];
                ldsm4(ah, sb + SQHI + qoffA + ks * 32);
                ldsm4(al, sb + SQLO + qoffA + ks * 32);
                uint32_t kh0[4], kh1[4];
                ldsm4(kh0, stg + SKH + kBoff + ks * 32);
                ldsm4(kh1, stg + SKH + kBoff + 16 * AQ_STRIDE + ks * 32);
                mma_f16(S[0], ah, kh0 + 0); mma_f16(S[1], ah, kh0 + 2);
                mma_f16(S[2], ah, kh1 + 0); mma_f16(S[3], ah, kh1 + 2);
                mma_f16(S[0], al, kh0 + 0); mma_f16(S[1], al, kh0 + 2);
                mma_f16(S[2], al, kh1 + 0); mma_f16(S[3], al, kh1 + 2);
            }

            // ---- mask + tile row max ----
            const uint32_t kidb = sb + SKID + s * 256;
            float mt0 = -1e30f, mt1 = -1e30f;
#pragma unroll
            for (int nf = 0; nf < 4; nf++) {
                int lc = wn * 32 + nf * 8 + 2 * (lane & 3);
                int kv0, kv1;
                asm volatile("ld.shared.v2.u32 {%0,%1}, [%2];"
                             : "=r"(kv0), "=r"(kv1) : "r"(kidb + lc * 4));
                int key = k0 + lc;
                if (key     > qrow0 || kv0 != qidv0) S[nf][0] = -1e30f;
                if (key + 1 > qrow0 || kv1 != qidv0) S[nf][1] = -1e30f;
                if (key     > qrow1 || kv0 != qidv1) S[nf][2] = -1e30f;
                if (key + 1 > qrow1 || kv1 != qidv1) S[nf][3] = -1e30f;
                mt0 = fmaxf(mt0, fmaxf(S[nf][0], S[nf][1]));
                mt1 = fmaxf(mt1, fmaxf(S[nf][2], S[nf][3]));
            }
            mt0 = fmaxf(mt0, __shfl_xor_sync(0xffffffffu, mt0, 1));
            mt0 = fmaxf(mt0, __shfl_xor_sync(0xffffffffu, mt0, 2));
            mt1 = fmaxf(mt1, __shfl_xor_sync(0xffffffffu, mt1, 1));
            mt1 = fmaxf(mt1, __shfl_xor_sync(0xffffffffu, mt1, 2));
            if ((lane & 3) == 0) {
                pmax[wn * 64 + row0] = mt0;
                pmax[wn * 64 + row1] = mt1;
            }
            __syncthreads();

            float mn0 = fmaxf(m0r, fmaxf(pmax[row0], pmax[64 + row0]));
            float mn1 = fmaxf(m1r, fmaxf(pmax[row1], pmax[64 + row1]));
            float f0 = __expf(m0r - mn0), f1 = __expf(m1r - mn1);
            m0r = mn0; m1r = mn1;

            float rs0 = 0.f, rs1 = 0.f;
#pragma unroll
            for (int nf = 0; nf < 4; nf++) {
                float p0 = (S[nf][0] < -1e29f) ? 0.f : __expf(S[nf][0] - mn0);
                float p1 = (S[nf][1] < -1e29f) ? 0.f : __expf(S[nf][1] - mn0);
                float p2 = (S[nf][2] < -1e29f) ? 0.f : __expf(S[nf][2] - mn1);
                float p3 = (S[nf][3] < -1e29f) ? 0.f : __expf(S[nf][3] - mn1);
                S[nf][0] = p0; S[nf][1] = p1; S[nf][2] = p2; S[nf][3] = p3;
                rs0 += p0 + p1; rs1 += p2 + p3;
            }
            rs0 += __shfl_xor_sync(0xffffffffu, rs0, 1);
            rs0 += __shfl_xor_sync(0xffffffffu, rs0, 2);
            rs1 += __shfl_xor_sync(0xffffffffu, rs1, 1);
            rs1 += __shfl_xor_sync(0xffffffffu, rs1, 2);
            l0r = l0r * f0 + rs0;
            l1r = l1r * f1 + rs1;

            // rescale O
#pragma unroll
            for (int nb = 0; nb < 16; nb++) {
                O[nb][0] *= f0; O[nb][1] *= f0;
                O[nb][2] *= f1; O[nb][3] *= f1;
            }

            // ---- O += RN16(P)·V (single product) ----
#pragma unroll
            for (int ks2 = 0; ks2 < 2; ks2++) {
                uint32_t ah[4];
                ah[0] = packh2(S[2 * ks2][0],     S[2 * ks2][1]);
                ah[1] = packh2(S[2 * ks2][2],     S[2 * ks2][3]);
                ah[2] = packh2(S[2 * ks2 + 1][0], S[2 * ks2 + 1][1]);
                ah[3] = packh2(S[2 * ks2 + 1][2], S[2 * ks2 + 1][3]);
                uint32_t ro = vBoff + ks2 * 16 * AQ_STRIDE;
#pragma unroll
                for (int np = 0; np < 4; np++) {
                    uint32_t vh0[4], vh1[4];
                    ldsm4t(vh0, stg + SVH + ro + (2 * np) * 32);
                    ldsm4t(vh1, stg + SVH + ro + (2 * np + 1) * 32);
                    int o0 = 4 * np;
                    mma_f16(O[o0 + 0], ah, vh0 + 0); mma_f16(O[o0 + 1], ah, vh0 + 2);
                    mma_f16(O[o0 + 2], ah, vh1 + 0); mma_f16(O[o0 + 3], ah, vh1 + 2);
                }
            }
        }
        __syncthreads();
    }

    // ---- epilogue: combine l across warp pairs, then O, then write planes ----
    if ((lane & 3) == 0) {
        lsum[wn * 64 + row0] = l0r;
        lsum[wn * 64 + row1] = l1r;
    }
    __syncthreads();
    float inv0 = 1.f / (lsum[row0] + lsum[64 + row0]);
    float inv1 = 1.f / (lsum[row1] + lsum[64 + row1]);

    if (wn == 1) {
#pragma unroll
        for (int nb = 0; nb < 16; nb++) {
            uint32_t off = (uint32_t)(wm * 8192 + lr * 512 + (nb * 8 + 2 * (lane & 3)) * 4);
            *(float2*)(smem + off) = make_float2(O[nb][0], O[nb][1]);
            *(float2*)(smem + off + 8 * 512) = make_float2(O[nb][2], O[nb][3]);
        }
    }
    __syncthreads();
    if (wn == 0) {
        const size_t g0 = ((size_t)b * S_LEN + qrow0) * DIM + h * HD;
        const size_t g1 = ((size_t)b * S_LEN + qrow1) * DIM + h * HD;
#pragma unroll
        for (int nb = 0; nb < 16; nb++) {
            int col = nb * 8 + 2 * (lane & 3);
            uint32_t off = (uint32_t)(wm * 8192 + lr * 512 + col * 4);
            float2 o0 = *(float2*)(smem + off);
            float2 o1 = *(float2*)(smem + off + 8 * 512);
            uint32_t hh, ll;
            split_f16x2((O[nb][0] + o0.x) * inv0, (O[nb][1] + o0.y) * inv0, hh, ll);
            *(uint32_t*)(ohi + g0 + col) = hh;
            *(uint32_t*)(olo + g0 + col) = ll;
            split_f16x2((O[nb][2] + o1.x) * inv1, (O[nb][3] + o1.y) * inv1, hh, ll);
            *(uint32_t*)(ohi + g1 + col) = hh;
            *(uint32_t*)(olo + g1 + col) = ll;
        }
    }
}

// ---------------------------------------------------------------------------
extern "C" void kernel_launch(void* const* d_in, const int* in_sizes, int n_in,
                              void* d_out, int out_size)
{
    const float* x    = (const float*)d_in[0];   // [4,2048,2048]
    const int*   ids  = (const int*)d_in[1];     // [4,2048]
    const float* Wqkv = (const float*)d_in[2];   // [2048,6144]
    const float* bqkv = (const float*)d_in[3];   // [6144]
    const float* Wo   = (const float*)d_in[4];   // [2048,2048]
    const float* bo   = (const float*)d_in[5];   // [2048]
    float* out = (float*)d_out;

    __half *qhi, *qlo, *khi, *vhi;
    __half *xhi, *xlo, *ahi, *alo, *wqh, *woh;
    cudaGetSymbolAddress((void**)&qhi, g_qhi);
    cudaGetSymbolAddress((void**)&qlo, g_qlo);
    cudaGetSymbolAddress((void**)&khi, g_khi);
    cudaGetSymbolAddress((void**)&vhi, g_vhi);
    cudaGetSymbolAddress((void**)&xhi, g_xhi);
    cudaGetSymbolAddress((void**)&xlo, g_xlo);
    cudaGetSymbolAddress((void**)&ahi, g_ahi);
    cudaGetSymbolAddress((void**)&alo, g_alo);
    cudaGetSymbolAddress((void**)&wqh, g_wqh);
    cudaGetSymbolAddress((void**)&woh, g_woh);

    cudaFuncSetAttribute(gemm2_out_kernel,
                         cudaFuncAttributeMaxDynamicSharedMemorySize, GSMEM_BYTES);
    cudaFuncSetAttribute(gemm2_qkv_kernel,
                         cudaFuncAttributeMaxDynamicSharedMemorySize, GSMEM_BYTES);
    cudaFuncSetAttribute(attn_mma_kernel,
                         cudaFuncAttributeMaxDynamicSharedMemorySize, ATTN_SMEM);

    const int M = BATCH * S_LEN;   // 8192

    // 0) pre-split x, round+transpose weights (one-shot)
    split_kernel<<<1184, 256>>>(x, xhi, xlo, (size_t)M * DIM / 2);
    {
        dim3 blk(32, 8);
        transpose_round_kernel<<<dim3(3 * DIM / 32, DIM / 32), blk>>>(Wqkv, wqh, DIM, 3 * DIM);
        transpose_round_kernel<<<dim3(DIM / 32, DIM / 32), blk>>>(Wo, woh, DIM, DIM);
    }
    // 1) QKV = x @ Wqkv + bqkv -> fp16 planes (Q 2-plane pre-scaled; K,V rounded)
    {
        dim3 grid(3 * DIM / 128, M / 128);
        gemm2_qkv_kernel<<<grid, 256, GSMEM_BYTES>>>(
            xhi, xlo, wqh, bqkv, qhi, qlo, khi, vhi, 3 * DIM, DIM);
    }
    // 2) flash attention -> fp16 hi/lo planes
    {
        dim3 grid(S_LEN / 64, HEADS, BATCH);
        attn_mma_kernel<<<grid, 256, ATTN_SMEM>>>(
            ids, ahi, alo, qhi, qlo, khi, vhi);
    }
    // 3) out = attn @ Wo + bo  [8192, 2048] fp32
    {
        dim3 grid(DIM / 128, M / 128);
        gemm2_out_kernel<<<grid, 256, GSMEM_BYTES>>>(
            ahi, alo, woh, bo, out, DIM, DIM);
    }
}

// round 9
// speedup vs baseline: 2.2088x; 1.2502x over previous
#include <cuda_runtime.h>
#include <cuda_fp16.h>
#include <cstdint>
#include <cstddef>

#define S_LEN 2048
#define DIM   2048
#define HEADS 16
#define HD    128
#define BATCH 4

// Scratch (allocation-free rule: __device__ globals)
#define PLANE_ELEMS ((size_t)BATCH * HEADS * S_LEN * HD)
__device__ __half g_qhi[PLANE_ELEMS], g_qlo[PLANE_ELEMS];
__device__ __half g_khi[PLANE_ELEMS];
__device__ __half g_vhi[PLANE_ELEMS];
__device__ __half g_xhi[(size_t)BATCH * S_LEN * DIM], g_xlo[(size_t)BATCH * S_LEN * DIM];
__device__ __half g_ahi[(size_t)BATCH * S_LEN * DIM];
__device__ __half g_wqh[(size_t)(3 * DIM) * DIM];
__device__ __half g_woh[(size_t)DIM * DIM];

// ---------------------------------------------------------------------------
// helpers
// ---------------------------------------------------------------------------
__device__ __forceinline__ uint32_t smem_to_u32(const void* p) {
    uint32_t a;
    asm("{ .reg .u64 t; cvta.to.shared.u64 t, %1; cvt.u32.u64 %0, t; }"
        : "=r"(a) : "l"(p));
    return a;
}

__device__ __forceinline__ void ldsm4(uint32_t* r, uint32_t addr) {
    asm volatile("ldmatrix.sync.aligned.m8n8.x4.shared.b16 {%0,%1,%2,%3}, [%4];"
                 : "=r"(r[0]), "=r"(r[1]), "=r"(r[2]), "=r"(r[3]) : "r"(addr));
}

__device__ __forceinline__ void ldsm4t(uint32_t* r, uint32_t addr) {
    asm volatile("ldmatrix.sync.aligned.m8n8.x4.trans.shared.b16 {%0,%1,%2,%3}, [%4];"
                 : "=r"(r[0]), "=r"(r[1]), "=r"(r[2]), "=r"(r[3]) : "r"(addr));
}

__device__ __forceinline__ void mma_f16(float* d, const uint32_t* a, const uint32_t* b) {
    asm volatile(
        "mma.sync.aligned.m16n8k16.row.col.f32.f16.f16.f32 "
        "{%0,%1,%2,%3}, {%4,%5,%6,%7}, {%8,%9}, {%0,%1,%2,%3};"
        : "+f"(d[0]), "+f"(d[1]), "+f"(d[2]), "+f"(d[3])
        : "r"(a[0]), "r"(a[1]), "r"(a[2]), "r"(a[3]), "r"(b[0]), "r"(b[1]));
}

// pack (x0,x1) -> fp16x2 (low half = x0)
__device__ __forceinline__ uint32_t packh2(float x0, float x1) {
    __half2 h = __floats2half2_rn(x0, x1);
    return *(uint32_t*)&h;
}

// x -> hi + lo, both fp16 (hi = RN(x), lo = RN(x - hi)); pair-packed
__device__ __forceinline__ void split_f16x2(float x0, float x1,
                                            uint32_t& hi, uint32_t& lo) {
    __half2 h = __floats2half2_rn(x0, x1);
    hi = *(uint32_t*)&h;
    float h0 = __low2float(h), h1 = __high2float(h);
    __half2 l = __floats2half2_rn(x0 - h0, x1 - h1);
    lo = *(uint32_t*)&l;
}

#define CP_ASYNC16(dst, src) \
    asm volatile("cp.async.cg.shared.global [%0], [%1], 16;" \
                 :: "r"(dst), "l"(src) : "memory")
#define CP_COMMIT() asm volatile("cp.async.commit_group;" ::: "memory")
#define CP_WAIT1()  asm volatile("cp.async.wait_group 1;" ::: "memory")

// ---------------------------------------------------------------------------
// Elementwise split: fp32 -> fp16 hi/lo planes
// ---------------------------------------------------------------------------
__global__ __launch_bounds__(256) void split_kernel(
    const float* __restrict__ in,
    __half* __restrict__ hi, __half* __restrict__ lo, size_t n2)
{
    size_t i = (size_t)blockIdx.x * blockDim.x + threadIdx.x;
    size_t stride = (size_t)gridDim.x * blockDim.x;
    for (; i < n2; i += stride) {
        float2 v = *(const float2*)(in + 2 * i);
        uint32_t h, l;
        split_f16x2(v.x, v.y, h, l);
        *(uint32_t*)(hi + 2 * i) = h;
        *(uint32_t*)(lo + 2 * i) = l;
    }
}

// ---------------------------------------------------------------------------
// Transpose + round: fp32 in[R][C] -> fp16 out[C][R]
// ---------------------------------------------------------------------------
__global__ __launch_bounds__(256) void transpose_round_kernel(
    const float* __restrict__ in, __half* __restrict__ out, int R, int C)
{
    __shared__ float t[32][33];
    int bx = blockIdx.x * 32;
    int by = blockIdx.y * 32;
    int x = threadIdx.x, y = threadIdx.y;   // 32 x 8
#pragma unroll
    for (int j = 0; j < 32; j += 8)
        t[y + j][x] = in[(size_t)(by + y + j) * C + bx + x];
    __syncthreads();
#pragma unroll
    for (int jj = 0; jj < 2; jj++) {
        int cp = y + 8 * jj;                 // 0..15 col pair index
        uint32_t h = packh2(t[cp * 2][x], t[cp * 2 + 1][x]);
        size_t o = (size_t)(bx + x) * R + by + cp * 2;
        *(uint32_t*)(out + o) = h;
    }
}

// ---------------------------------------------------------------------------
// fp16 GEMM: C = (Ahi[+Alo]) @ Bh^T (+bias); lo product gated by do_lo.
// 128x128 tile, BK=32, 256 threads, 3-stage cp.async pipeline, 2 CTAs/SM.
// Stage layout (row stride 80B): Ahi@0  Alo@10240  Bh@20480  (30720 B/stage)
// One barrier per mainloop iter (top-of-iter covers the WAR hazard).
// Requires before expansion: const bool do_lo.
// ---------------------------------------------------------------------------
#define GSTRIDE      80
#define GSTAGE_BYTES 30720
#define GSMEM_BYTES  (3 * GSTAGE_BYTES)

#define GEMM_PL_BODY                                                          \
    extern __shared__ __align__(1024) char smem[];                            \
    const uint32_t sb = smem_to_u32(smem);                                    \
    const int tid = threadIdx.x;                                              \
    const int wid = tid >> 5, lid = tid & 31;                                 \
    const int wm = wid >> 1;                                                  \
    const int wn = wid & 1;                                                   \
    const uint32_t aBase = (uint32_t)((wm * 32 + (lid & 15)) * GSTRIDE + (lid >> 4) * 16); \
    const uint32_t bBase = (uint32_t)((wn * 64 + ((lid >> 1) & 8) + (lid & 7)) * GSTRIDE \
                                      + ((lid & 8) << 1));                    \
    const int lrow = tid >> 1;                                                \
    const int lc0 = (tid & 1) * 2;                                            \
    float acc[2][8][4];                                                       \
    _Pragma("unroll")                                                         \
    for (int mf = 0; mf < 2; mf++)                                            \
        _Pragma("unroll")                                                     \
        for (int nf = 0; nf < 8; nf++)                                        \
            _Pragma("unroll")                                                 \
            for (int q = 0; q < 4; q++) acc[mf][nf][q] = 0.f;                 \
    const int niter = K >> 5;                                                 \
    auto issue = [&](int i, int s) {                                          \
        const int k0 = i << 5;                                                \
        const uint32_t base = sb + s * GSTAGE_BYTES;                          \
        const uint32_t so = (uint32_t)(lrow * GSTRIDE + lc0 * 16);            \
        const size_t ga = (size_t)(m0 + lrow) * K + k0 + lc0 * 8;             \
        const size_t gb = (size_t)(n0 + lrow) * K + k0 + lc0 * 8;             \
        CP_ASYNC16(base + so,              (const char*)(Ahi + ga));          \
        CP_ASYNC16(base + so + 16,         (const char*)(Ahi + ga + 8));      \
        if (do_lo) {                                                          \
            CP_ASYNC16(base + 10240 + so,      (const char*)(Alo + ga));      \
            CP_ASYNC16(base + 10240 + so + 16, (const char*)(Alo + ga + 8));  \
        }                                                                     \
        CP_ASYNC16(base + 20480 + so,      (const char*)(Bh + gb));           \
        CP_ASYNC16(base + 20480 + so + 16, (const char*)(Bh + gb + 8));       \
    };                                                                        \
    issue(0, 0); CP_COMMIT();                                                 \
    if (niter > 1) { issue(1, 1); CP_COMMIT(); }                              \
    for (int i = 0; i < niter; i++) {                                         \
        const int s = i % 3;                                                  \
        CP_WAIT1();                                                           \
        __syncthreads();                                                      \
        if (i + 2 < niter) issue(i + 2, (i + 2) % 3);                         \
        CP_COMMIT();                                                          \
        const uint32_t sA = sb + s * GSTAGE_BYTES;                            \
        _Pragma("unroll")                                                     \
        for (int kstep = 0; kstep < 2; kstep++) {                             \
            const uint32_t koff = kstep * 32;                                 \
            uint32_t ahi[2][4], alo[2][4];                                    \
            ldsm4(ahi[0], sA + aBase + koff);                                 \
            ldsm4(ahi[1], sA + aBase + 16 * GSTRIDE + koff);                  \
            if (do_lo) {                                                      \
                ldsm4(alo[0], sA + 10240 + aBase + koff);                     \
                ldsm4(alo[1], sA + 10240 + aBase + 16 * GSTRIDE + koff);      \
            }                                                                 \
            uint32_t bh[8][2];                                                \
            _Pragma("unroll")                                                 \
            for (int t2 = 0; t2 < 4; t2++) {                                  \
                uint32_t r[4];                                                \
                ldsm4(r, sA + 20480 + bBase + t2 * 16 * GSTRIDE + koff);      \
                bh[2 * t2][0] = r[0]; bh[2 * t2][1] = r[1];                   \
                bh[2 * t2 + 1][0] = r[2]; bh[2 * t2 + 1][1] = r[3];           \
            }                                                                 \
            _Pragma("unroll")                                                 \
            for (int mf = 0; mf < 2; mf++)                                    \
                _Pragma("unroll")                                             \
                for (int nf = 0; nf < 8; nf++)                                \
                    mma_f16(acc[mf][nf], ahi[mf], bh[nf]);                    \
            if (do_lo) {                                                      \
                _Pragma("unroll")                                             \
                for (int mf = 0; mf < 2; mf++)                                \
                    _Pragma("unroll")                                         \
                    for (int nf = 0; nf < 8; nf++)                            \
                        mma_f16(acc[mf][nf], alo[mf], bh[nf]);                \
            }                                                                 \
        }                                                                     \
    }                                                                         \
    __syncthreads();

// fp32 output GEMM (output projection) — single product (A rounded fp16)
__global__ __launch_bounds__(256, 2) void gemm2_out_kernel(
    const __half* __restrict__ Ahi, const __half* __restrict__ Bh,
    const float* __restrict__ bias, float* __restrict__ C, int N, int K)
{
    const __half* Alo = Ahi;          // unused (do_lo = false)
    const bool do_lo = false;
    const int m0 = blockIdx.y * 128;
    const int n0 = blockIdx.x * 128;
    GEMM_PL_BODY
    const int erow = m0 + wm * 32 + (lid >> 2);
    const int ecol0 = n0 + wn * 64 + (lid & 3) * 2;
#pragma unroll
    for (int mf = 0; mf < 2; mf++) {
#pragma unroll
        for (int nf = 0; nf < 8; nf++) {
            int col = ecol0 + nf * 8;
            float2 bz = *(const float2*)(bias + col);
            float2 v0, v1;
            v0.x = acc[mf][nf][0] + bz.x; v0.y = acc[mf][nf][1] + bz.y;
            v1.x = acc[mf][nf][2] + bz.x; v1.y = acc[mf][nf][3] + bz.y;
            size_t r0 = (size_t)(erow + mf * 16) * N + col;
            *(float2*)(C + r0) = v0;
            *(float2*)(C + r0 + 8 * N) = v1;
        }
    }
}

// QKV GEMM: Q columns 2-product (do_lo), K/V columns single product.
// Q -> fp16 2-plane (pre-scaled); K,V -> fp16 single plane.
__global__ __launch_bounds__(256, 2) void gemm2_qkv_kernel(
    const __half* __restrict__ Ahi, const __half* __restrict__ Alo,
    const __half* __restrict__ Bh,
    const float* __restrict__ bias,
    __half* __restrict__ qhi, __half* __restrict__ qlo,
    __half* __restrict__ khi, __half* __restrict__ vhi,
    int N, int K)
{
    const int m0 = blockIdx.y * 128;
    const int n0 = blockIdx.x * 128;
    const bool do_lo = (n0 >> 11) == 0;   // Q third only
    GEMM_PL_BODY
    const int t = n0 >> 11;                 // 0=Q 1=K 2=V
    const int head = (n0 >> 7) & (HEADS - 1);
    const int erow = m0 + wm * 32 + (lid >> 2);
    const int lcol0 = wn * 64 + (lid & 3) * 2;
#pragma unroll
    for (int mf = 0; mf < 2; mf++) {
        int tok0 = erow + mf * 16;
        int b = tok0 >> 11;
        int s0 = tok0 & 2047;
        size_t pb = ((size_t)(b * HEADS + head) * S_LEN) * HD;
#pragma unroll
        for (int nf = 0; nf < 8; nf++) {
            int lc = lcol0 + nf * 8;
            float2 bz = *(const float2*)(bias + n0 + lc);
            float v0 = acc[mf][nf][0] + bz.x;
            float v1 = acc[mf][nf][1] + bz.y;
            float v2 = acc[mf][nf][2] + bz.x;
            float v3 = acc[mf][nf][3] + bz.y;
            size_t p0 = pb + (size_t)s0 * HD + lc;
            size_t p1 = pb + (size_t)(s0 + 8) * HD + lc;
            if (t == 0) {
                const float sc = 0.08838834764831845f;
                uint32_t h, l;
                split_f16x2(v0 * sc, v1 * sc, h, l);
                *(uint32_t*)(qhi + p0) = h;
                *(uint32_t*)(qlo + p0) = l;
                split_f16x2(v2 * sc, v3 * sc, h, l);
                *(uint32_t*)(qhi + p1) = h;
                *(uint32_t*)(qlo + p1) = l;
            } else {
                __half* p = (t == 1) ? khi : vhi;
                *(uint32_t*)(p + p0) = packh2(v0, v1);
                *(uint32_t*)(p + p1) = packh2(v2, v3);
            }
        }
    }
}

// ---------------------------------------------------------------------------
// Tensor-core flash attention (fp16): S = (Qhi+Qlo)·K^T (2 products),
// O += RN16(P)·V (1 product). Segment+causal mask, segment skip.
// grid (32, HEADS, BATCH), 256 threads = 8 warps (4 m-slabs x 2 key-slabs).
// Output: single fp16 plane of the normalized attention output.
// ---------------------------------------------------------------------------
#define AQ_STRIDE 272                 // smem bytes per row (128 fp16 + pad)
#define SQHI 0
#define SQLO 17408
#define SSTAGE0 34816
#define SSTAGE_BYTES 34816            // Kh, Vh
#define SKH 0
#define SVH 17408
#define SKID  104448                  // + stage*256
#define SPMAX 104960
#define SLSUM 105472
#define ATTN_SMEM 105984

__global__ __launch_bounds__(256, 1) void attn_mma_kernel(
    const int* __restrict__ ids,
    __half* __restrict__ ohi,
    const __half* __restrict__ qhi, const __half* __restrict__ qlo,
    const __half* __restrict__ khi, const __half* __restrict__ vhi)
{
    extern __shared__ __align__(1024) char smem[];
    const uint32_t sb = smem_to_u32(smem);
    const int tid = threadIdx.x;
    const int lane = tid & 31, wid = tid >> 5;
    const int wm = wid >> 1, wn = wid & 1;
    const int b = blockIdx.z, h = blockIdx.y;
    const int qt = gridDim.x - 1 - blockIdx.x;       // big tiles first
    const int q0 = qt * 64;
    const size_t pbase = (size_t)(b * HEADS + h) * S_LEN * HD;
    const int* bids = ids + b * S_LEN;

    const int lr = lane >> 2;
    const int row0 = wm * 16 + lr, row1 = row0 + 8;
    const int qrow0 = q0 + row0, qrow1 = q0 + row1;
    const int qidv0 = bids[qrow0], qidv1 = bids[qrow1];
    const int qid_min = bids[q0];

    float* pmax = (float*)(smem + SPMAX);
    float* lsum = (float*)(smem + SLSUM);

    auto issue_tile = [&](int kb, int s) {
        const int k0 = kb * 64;
        const uint32_t stg = sb + SSTAGE0 + s * SSTAGE_BYTES;
#pragma unroll
        for (int j = 0; j < 4; j++) {
            int q = tid + 256 * j;
            int key = q >> 4, c16 = q & 15;
            uint32_t soff = (uint32_t)(key * AQ_STRIDE + c16 * 16);
            size_t goff = pbase + (size_t)(k0 + key) * HD + c16 * 8;
            CP_ASYNC16(stg + SKH + soff, (const char*)(khi + goff));
            CP_ASYNC16(stg + SVH + soff, (const char*)(vhi + goff));
        }
        if (tid < 16)
            CP_ASYNC16(sb + SKID + s * 256 + tid * 16,
                       (const char*)(bids + k0 + tid * 4));
    };

    // ---- prologue: Q planes + tile 0 in cp.async group 0 ----
#pragma unroll
    for (int j = 0; j < 4; j++) {
        int q = tid + 256 * j;
        int key = q >> 4, c16 = q & 15;
        uint32_t soff = (uint32_t)(key * AQ_STRIDE + c16 * 16);
        size_t goff = pbase + (size_t)(q0 + key) * HD + c16 * 8;
        CP_ASYNC16(sb + SQHI + soff, (const char*)(qhi + goff));
        CP_ASYNC16(sb + SQLO + soff, (const char*)(qlo + goff));
    }
    issue_tile(0, 0);
    CP_COMMIT();

    float O[16][4];
#pragma unroll
    for (int nb = 0; nb < 16; nb++)
#pragma unroll
        for (int q = 0; q < 4; q++) O[nb][q] = 0.f;
    float m0r = -1e30f, m1r = -1e30f, l0r = 0.f, l1r = 0.f;

    const uint32_t qoffA = (uint32_t)((wm * 16 + (lane & 15)) * AQ_STRIDE + (lane >> 4) * 16);
    const uint32_t kBoff = (uint32_t)((wn * 32 + ((lane >> 1) & 8) + (lane & 7)) * AQ_STRIDE
                                      + ((lane & 8) << 1));
    const uint32_t vBoff = (uint32_t)((wn * 32 + ((lane >> 3) & 1) * 8 + (lane & 7)) * AQ_STRIDE
                                      + ((lane >> 4) & 1) * 16);

    const int nkb = qt;
    for (int kb = 0; kb <= nkb; kb++) {
        const int s = kb & 1;
        if (kb + 1 <= nkb) {
            bool skip_next = (bids[(kb + 1) * 64 + 63] < qid_min);
            if (!skip_next) issue_tile(kb + 1, s ^ 1);
        }
        CP_COMMIT();
        CP_WAIT1();
        __syncthreads();

        bool skip_cur = (bids[kb * 64 + 63] < qid_min);
        if (!skip_cur) {
            const uint32_t stg = sb + SSTAGE0 + s * SSTAGE_BYTES;
            const int k0 = kb * 64;

            // ---- S = (Qhi+Qlo)·K^T, 2 products, sweep-ordered ----
            float S[4][4];
#pragma unroll
            for (int nf = 0; nf < 4; nf++)
#pragma unroll
                for (int c = 0; c < 4; c++) S[nf][c] = 0.f;
#pragma unroll
            for (int ks = 0; ks < 8; ks++) {
                uint32_t ah[4], al[4];
                ldsm4(ah, sb + SQHI + qoffA + ks * 32);
                ldsm4(al, sb + SQLO + qoffA + ks * 32);
                uint32_t kh0[4], kh1[4];
                ldsm4(kh0, stg + SKH + kBoff + ks * 32);
                ldsm4(kh1, stg + SKH + kBoff + 16 * AQ_STRIDE + ks * 32);
                mma_f16(S[0], ah, kh0 + 0); mma_f16(S[1], ah, kh0 + 2);
                mma_f16(S[2], ah, kh1 + 0); mma_f16(S[3], ah, kh1 + 2);
                mma_f16(S[0], al, kh0 + 0); mma_f16(S[1], al, kh0 + 2);
                mma_f16(S[2], al, kh1 + 0); mma_f16(S[3], al, kh1 + 2);
            }

            // ---- mask + tile row max ----
            const uint32_t kidb = sb + SKID + s * 256;
            float mt0 = -1e30f, mt1 = -1e30f;
#pragma unroll
            for (int nf = 0; nf < 4; nf++) {
                int lc = wn * 32 + nf * 8 + 2 * (lane & 3);
                int kv0, kv1;
                asm volatile("ld.shared.v2.u32 {%0,%1}, [%2];"
                             : "=r"(kv0), "=r"(kv1) : "r"(kidb + lc * 4));
                int key = k0 + lc;
                if (key     > qrow0 || kv0 != qidv0) S[nf][0] = -1e30f;
                if (key + 1 > qrow0 || kv1 != qidv0) S[nf][1] = -1e30f;
                if (key     > qrow1 || kv0 != qidv1) S[nf][2] = -1e30f;
                if (key + 1 > qrow1 || kv1 != qidv1) S[nf][3] = -1e30f;
                mt0 = fmaxf(mt0, fmaxf(S[nf][0], S[nf][1]));
                mt1 = fmaxf(mt1, fmaxf(S[nf][2], S[nf][3]));
            }
            mt0 = fmaxf(mt0, __shfl_xor_sync(0xffffffffu, mt0, 1));
            mt0 = fmaxf(mt0, __shfl_xor_sync(0xffffffffu, mt0, 2));
            mt1 = fmaxf(mt1, __shfl_xor_sync(0xffffffffu, mt1, 1));
            mt1 = fmaxf(mt1, __shfl_xor_sync(0xffffffffu, mt1, 2));
            if ((lane & 3) == 0) {
                pmax[wn * 64 + row0] = mt0;
                pmax[wn * 64 + row1] = mt1;
            }
            __syncthreads();

            float mn0 = fmaxf(m0r, fmaxf(pmax[row0], pmax[64 + row0]));
            float mn1 = fmaxf(m1r, fmaxf(pmax[row1], pmax[64 + row1]));
            float f0 = __expf(m0r - mn0), f1 = __expf(m1r - mn1);
            m0r = mn0; m1r = mn1;

            float rs0 = 0.f, rs1 = 0.f;
#pragma unroll
            for (int nf = 0; nf < 4; nf++) {
                float p0 = (S[nf][0] < -1e29f) ? 0.f : __expf(S[nf][0] - mn0);
                float p1 = (S[nf][1] < -1e29f) ? 0.f : __expf(S[nf][1] - mn0);
                float p2 = (S[nf][2] < -1e29f) ? 0.f : __expf(S[nf][2] - mn1);
                float p3 = (S[nf][3] < -1e29f) ? 0.f : __expf(S[nf][3] - mn1);
                S[nf][0] = p0; S[nf][1] = p1; S[nf][2] = p2; S[nf][3] = p3;
                rs0 += p0 + p1; rs1 += p2 + p3;
            }
            rs0 += __shfl_xor_sync(0xffffffffu, rs0, 1);
            rs0 += __shfl_xor_sync(0xffffffffu, rs0, 2);
            rs1 += __shfl_xor_sync(0xffffffffu, rs1, 1);
            rs1 += __shfl_xor_sync(0xffffffffu, rs1, 2);
            l0r = l0r * f0 + rs0;
            l1r = l1r * f1 + rs1;

            // rescale O
#pragma unroll
            for (int nb = 0; nb < 16; nb++) {
                O[nb][0] *= f0; O[nb][1] *= f0;
                O[nb][2] *= f1; O[nb][3] *= f1;
            }

            // ---- O += RN16(P)·V (single product) ----
#pragma unroll
            for (int ks2 = 0; ks2 < 2; ks2++) {
                uint32_t ah[4];
                ah[0] = packh2(S[2 * ks2][0],     S[2 * ks2][1]);
                ah[1] = packh2(S[2 * ks2][2],     S[2 * ks2][3]);
                ah[2] = packh2(S[2 * ks2 + 1][0], S[2 * ks2 + 1][1]);
                ah[3] = packh2(S[2 * ks2 + 1][2], S[2 * ks2 + 1][3]);
                uint32_t ro = vBoff + ks2 * 16 * AQ_STRIDE;
#pragma unroll
                for (int np = 0; np < 4; np++) {
                    uint32_t vh0[4], vh1[4];
                    ldsm4t(vh0, stg + SVH + ro + (2 * np) * 32);
                    ldsm4t(vh1, stg + SVH + ro + (2 * np + 1) * 32);
                    int o0 = 4 * np;
                    mma_f16(O[o0 + 0], ah, vh0 + 0); mma_f16(O[o0 + 1], ah, vh0 + 2);
                    mma_f16(O[o0 + 2], ah, vh1 + 0); mma_f16(O[o0 + 3], ah, vh1 + 2);
                }
            }
        }
        __syncthreads();
    }

    // ---- epilogue: combine l across warp pairs, then O, then write plane ----
    if ((lane & 3) == 0) {
        lsum[wn * 64 + row0] = l0r;
        lsum[wn * 64 + row1] = l1r;
    }
    __syncthreads();
    float inv0 = 1.f / (lsum[row0] + lsum[64 + row0]);
    float inv1 = 1.f / (lsum[row1] + lsum[64 + row1]);

    if (wn == 1) {
#pragma unroll
        for (int nb = 0; nb < 16; nb++) {
            uint32_t off = (uint32_t)(wm * 8192 + lr * 512 + (nb * 8 + 2 * (lane & 3)) * 4);
            *(float2*)(smem + off) = make_float2(O[nb][0], O[nb][1]);
            *(float2*)(smem + off + 8 * 512) = make_float2(O[nb][2], O[nb][3]);
        }
    }
    __syncthreads();
    if (wn == 0) {
        const size_t g0 = ((size_t)b * S_LEN + qrow0) * DIM + h * HD;
        const size_t g1 = ((size_t)b * S_LEN + qrow1) * DIM + h * HD;
#pragma unroll
        for (int nb = 0; nb < 16; nb++) {
            int col = nb * 8 + 2 * (lane & 3);
            uint32_t off = (uint32_t)(wm * 8192 + lr * 512 + col * 4);
            float2 o0 = *(float2*)(smem + off);
            float2 o1 = *(float2*)(smem + off + 8 * 512);
            *(uint32_t*)(ohi + g0 + col) =
                packh2((O[nb][0] + o0.x) * inv0, (O[nb][1] + o0.y) * inv0);
            *(uint32_t*)(ohi + g1 + col) =
                packh2((O[nb][2] + o1.x) * inv1, (O[nb][3] + o1.y) * inv1);
        }
    }
}

// ---------------------------------------------------------------------------
extern "C" void kernel_launch(void* const* d_in, const int* in_sizes, int n_in,
                              void* d_out, int out_size)
{
    const float* x    = (const float*)d_in[0];   // [4,2048,2048]
    const int*   ids  = (const int*)d_in[1];     // [4,2048]
    const float* Wqkv = (const float*)d_in[2];   // [2048,6144]
    const float* bqkv = (const float*)d_in[3];   // [6144]
    const float* Wo   = (const float*)d_in[4];   // [2048,2048]
    const float* bo   = (const float*)d_in[5];   // [2048]
    float* out = (float*)d_out;

    __half *qhi, *qlo, *khi, *vhi;
    __half *xhi, *xlo, *ahi, *wqh, *woh;
    cudaGetSymbolAddress((void**)&qhi, g_qhi);
    cudaGetSymbolAddress((void**)&qlo, g_qlo);
    cudaGetSymbolAddress((void**)&khi, g_khi);
    cudaGetSymbolAddress((void**)&vhi, g_vhi);
    cudaGetSymbolAddress((void**)&xhi, g_xhi);
    cudaGetSymbolAddress((void**)&xlo, g_xlo);
    cudaGetSymbolAddress((void**)&ahi, g_ahi);
    cudaGetSymbolAddress((void**)&wqh, g_wqh);
    cudaGetSymbolAddress((void**)&woh, g_woh);

    cudaFuncSetAttribute(gemm2_out_kernel,
                         cudaFuncAttributeMaxDynamicSharedMemorySize, GSMEM_BYTES);
    cudaFuncSetAttribute(gemm2_qkv_kernel,
                         cudaFuncAttributeMaxDynamicSharedMemorySize, GSMEM_BYTES);
    cudaFuncSetAttribute(attn_mma_kernel,
                         cudaFuncAttributeMaxDynamicSharedMemorySize, ATTN_SMEM);

    const int M = BATCH * S_LEN;   // 8192

    // 0) pre-split x, round+transpose weights (one-shot)
    split_kernel<<<1184, 256>>>(x, xhi, xlo, (size_t)M * DIM / 2);
    {
        dim3 blk(32, 8);
        transpose_round_kernel<<<dim3(3 * DIM / 32, DIM / 32), blk>>>(Wqkv, wqh, DIM, 3 * DIM);
        transpose_round_kernel<<<dim3(DIM / 32, DIM / 32), blk>>>(Wo, woh, DIM, DIM);
    }
    // 1) QKV: Q 2-product -> 2-plane (pre-scaled); K,V 1-product -> 1 plane
    {
        dim3 grid(3 * DIM / 128, M / 128);
        gemm2_qkv_kernel<<<grid, 256, GSMEM_BYTES>>>(
            xhi, xlo, wqh, bqkv, qhi, qlo, khi, vhi, 3 * DIM, DIM);
    }
    // 2) flash attention -> single fp16 plane
    {
        dim3 grid(S_LEN / 64, HEADS, BATCH);
        attn_mma_kernel<<<grid, 256, ATTN_SMEM>>>(
            ids, ahi, qhi, qlo, khi, vhi);
    }
    // 3) out = attn @ Wo + bo  [8192, 2048] fp32, single product
    {
        dim3 grid(DIM / 128, M / 128);
        gemm2_out_kernel<<<grid, 256, GSMEM_BYTES>>>(
            ahi, woh, bo, out, DIM, DIM);
    }
}

// round 10
// speedup vs baseline: 3.1192x; 1.4121x over previous
#include <cuda_runtime.h>
#include <cuda_fp16.h>
#include <cstdint>
#include <cstddef>

#define S_LEN 2048
#define DIM   2048
#define HEADS 16
#define HD    128
#define BATCH 4

// Scratch (allocation-free rule: __device__ globals)
#define PLANE_ELEMS ((size_t)BATCH * HEADS * S_LEN * HD)
__device__ __half g_qh[PLANE_ELEMS];
__device__ __half g_kh[PLANE_ELEMS];
__device__ __half g_vh[PLANE_ELEMS];
__device__ __half g_xh[(size_t)BATCH * S_LEN * DIM];
__device__ __half g_ah[(size_t)BATCH * S_LEN * DIM];
__device__ __half g_wqh[(size_t)(3 * DIM) * DIM];
__device__ __half g_woh[(size_t)DIM * DIM];

// ---------------------------------------------------------------------------
// helpers
// ---------------------------------------------------------------------------
__device__ __forceinline__ uint32_t smem_to_u32(const void* p) {
    uint32_t a;
    asm("{ .reg .u64 t; cvta.to.shared.u64 t, %1; cvt.u32.u64 %0, t; }"
        : "=r"(a) : "l"(p));
    return a;
}

__device__ __forceinline__ void ldsm4(uint32_t* r, uint32_t addr) {
    asm volatile("ldmatrix.sync.aligned.m8n8.x4.shared.b16 {%0,%1,%2,%3}, [%4];"
                 : "=r"(r[0]), "=r"(r[1]), "=r"(r[2]), "=r"(r[3]) : "r"(addr));
}

__device__ __forceinline__ void ldsm4t(uint32_t* r, uint32_t addr) {
    asm volatile("ldmatrix.sync.aligned.m8n8.x4.trans.shared.b16 {%0,%1,%2,%3}, [%4];"
                 : "=r"(r[0]), "=r"(r[1]), "=r"(r[2]), "=r"(r[3]) : "r"(addr));
}

__device__ __forceinline__ void mma_f16(float* d, const uint32_t* a, const uint32_t* b) {
    asm volatile(
        "mma.sync.aligned.m16n8k16.row.col.f32.f16.f16.f32 "
        "{%0,%1,%2,%3}, {%4,%5,%6,%7}, {%8,%9}, {%0,%1,%2,%3};"
        : "+f"(d[0]), "+f"(d[1]), "+f"(d[2]), "+f"(d[3])
        : "r"(a[0]), "r"(a[1]), "r"(a[2]), "r"(a[3]), "r"(b[0]), "r"(b[1]));
}

// pack (x0,x1) -> fp16x2 (low half = x0)
__device__ __forceinline__ uint32_t packh2(float x0, float x1) {
    __half2 h = __floats2half2_rn(x0, x1);
    return *(uint32_t*)&h;
}

#define CP_ASYNC16(dst, src) \
    asm volatile("cp.async.cg.shared.global [%0], [%1], 16;" \
                 :: "r"(dst), "l"(src) : "memory")
#define CP_COMMIT() asm volatile("cp.async.commit_group;" ::: "memory")
#define CP_WAIT1()  asm volatile("cp.async.wait_group 1;" ::: "memory")

// ---------------------------------------------------------------------------
// Elementwise round: fp32 -> fp16 plane
// ---------------------------------------------------------------------------
__global__ __launch_bounds__(256) void round_kernel(
    const float* __restrict__ in, __half* __restrict__ out, size_t n2)
{
    size_t i = (size_t)blockIdx.x * blockDim.x + threadIdx.x;
    size_t stride = (size_t)gridDim.x * blockDim.x;
    for (; i < n2; i += stride) {
        float2 v = *(const float2*)(in + 2 * i);
        *(uint32_t*)(out + 2 * i) = packh2(v.x, v.y);
    }
}

// ---------------------------------------------------------------------------
// Transpose + round: fp32 in[R][C] -> fp16 out[C][R]
// ---------------------------------------------------------------------------
__global__ __launch_bounds__(256) void transpose_round_kernel(
    const float* __restrict__ in, __half* __restrict__ out, int R, int C)
{
    __shared__ float t[32][33];
    int bx = blockIdx.x * 32;
    int by = blockIdx.y * 32;
    int x = threadIdx.x, y = threadIdx.y;   // 32 x 8
#pragma unroll
    for (int j = 0; j < 32; j += 8)
        t[y + j][x] = in[(size_t)(by + y + j) * C + bx + x];
    __syncthreads();
#pragma unroll
    for (int jj = 0; jj < 2; jj++) {
        int cp = y + 8 * jj;                 // 0..15 col pair index
        uint32_t h = packh2(t[cp * 2][x], t[cp * 2 + 1][x]);
        size_t o = (size_t)(bx + x) * R + by + cp * 2;
        *(uint32_t*)(out + o) = h;
    }
}

// ---------------------------------------------------------------------------
// fp16 single-product GEMM: C = Ah @ Bh^T (+bias).
// 128x128 tile, BK=64, 256 threads, 3-stage cp.async pipeline, 2 CTAs/SM.
// Stage (row stride 144B = 64 fp16 + 8 pad): Ah@0 (18432B)  Bh@18432
// One barrier per mainloop iter (top-of-iter covers the WAR hazard).
// ---------------------------------------------------------------------------
#define GSTRIDE      144
#define GB_OFF       18432
#define GSTAGE_BYTES 36864
#define GSMEM_BYTES  (3 * GSTAGE_BYTES)

#define GEMM1_BODY                                                            \
    extern __shared__ __align__(1024) char smem[];                            \
    const uint32_t sb = smem_to_u32(smem);                                    \
    const int tid = threadIdx.x;                                              \
    const int wid = tid >> 5, lid = tid & 31;                                 \
    const int wm = wid >> 1;                                                  \
    const int wn = wid & 1;                                                   \
    const uint32_t aBase = (uint32_t)((wm * 32 + (lid & 15)) * GSTRIDE + (lid >> 4) * 16); \
    const uint32_t bBase = (uint32_t)((wn * 64 + ((lid >> 1) & 8) + (lid & 7)) * GSTRIDE \
                                      + ((lid & 8) << 1));                    \
    float acc[2][8][4];                                                       \
    _Pragma("unroll")                                                         \
    for (int mf = 0; mf < 2; mf++)                                            \
        _Pragma("unroll")                                                     \
        for (int nf = 0; nf < 8; nf++)                                        \
            _Pragma("unroll")                                                 \
            for (int q = 0; q < 4; q++) acc[mf][nf][q] = 0.f;                 \
    const int niter = K >> 6;                                                 \
    auto issue = [&](int i, int s) {                                          \
        const int k0 = i << 6;                                                \
        const uint32_t base = sb + s * GSTAGE_BYTES;                          \
        _Pragma("unroll")                                                     \
        for (int j = 0; j < 4; j++) {                                         \
            int c = tid + 256 * j;                                            \
            int row = c >> 3, c8 = c & 7;                                     \
            uint32_t so = (uint32_t)(row * GSTRIDE + c8 * 16);                \
            CP_ASYNC16(base + so,          (const char*)(Ah + (size_t)(m0 + row) * K + k0 + c8 * 8)); \
            CP_ASYNC16(base + GB_OFF + so, (const char*)(Bh + (size_t)(n0 + row) * K + k0 + c8 * 8)); \
        }                                                                     \
    };                                                                        \
    issue(0, 0); CP_COMMIT();                                                 \
    if (niter > 1) { issue(1, 1); CP_COMMIT(); }                              \
    for (int i = 0; i < niter; i++) {                                         \
        const int s = i % 3;                                                  \
        CP_WAIT1();                                                           \
        __syncthreads();                                                      \
        if (i + 2 < niter) issue(i + 2, (i + 2) % 3);                         \
        CP_COMMIT();                                                          \
        const uint32_t sA = sb + s * GSTAGE_BYTES;                            \
        _Pragma("unroll")                                                     \
        for (int kstep = 0; kstep < 4; kstep++) {                             \
            const uint32_t koff = kstep * 32;                                 \
            uint32_t ah[2][4];                                                \
            ldsm4(ah[0], sA + aBase + koff);                                  \
            ldsm4(ah[1], sA + aBase + 16 * GSTRIDE + koff);                   \
            uint32_t bh[8][2];                                                \
            _Pragma("unroll")                                                 \
            for (int t2 = 0; t2 < 4; t2++) {                                  \
                uint32_t r[4];                                                \
                ldsm4(r, sA + GB_OFF + bBase + t2 * 16 * GSTRIDE + koff);     \
                bh[2 * t2][0] = r[0]; bh[2 * t2][1] = r[1];                   \
                bh[2 * t2 + 1][0] = r[2]; bh[2 * t2 + 1][1] = r[3];           \
            }                                                                 \
            _Pragma("unroll")                                                 \
            for (int mf = 0; mf < 2; mf++)                                    \
                _Pragma("unroll")                                             \
                for (int nf = 0; nf < 8; nf++)                                \
                    mma_f16(acc[mf][nf], ah[mf], bh[nf]);                     \
        }                                                                     \
    }                                                                         \
    __syncthreads();

// fp32 output GEMM (output projection)
__global__ __launch_bounds__(256, 2) void gemm1_out_kernel(
    const __half* __restrict__ Ah, const __half* __restrict__ Bh,
    const float* __restrict__ bias, float* __restrict__ C, int N, int K)
{
    const int m0 = blockIdx.y * 128;
    const int n0 = blockIdx.x * 128;
    GEMM1_BODY
    const int erow = m0 + wm * 32 + (lid >> 2);
    const int ecol0 = n0 + wn * 64 + (lid & 3) * 2;
#pragma unroll
    for (int mf = 0; mf < 2; mf++) {
#pragma unroll
        for (int nf = 0; nf < 8; nf++) {
            int col = ecol0 + nf * 8;
            float2 bz = *(const float2*)(bias + col);
            float2 v0, v1;
            v0.x = acc[mf][nf][0] + bz.x; v0.y = acc[mf][nf][1] + bz.y;
            v1.x = acc[mf][nf][2] + bz.x; v1.y = acc[mf][nf][3] + bz.y;
            size_t r0 = (size_t)(erow + mf * 16) * N + col;
            *(float2*)(C + r0) = v0;
            *(float2*)(C + r0 + 8 * N) = v1;
        }
    }
}

// QKV GEMM: all thirds single product -> single fp16 plane (Q pre-scaled)
__global__ __launch_bounds__(256, 2) void gemm1_qkv_kernel(
    const __half* __restrict__ Ah, const __half* __restrict__ Bh,
    const float* __restrict__ bias,
    __half* __restrict__ qh, __half* __restrict__ kh, __half* __restrict__ vh,
    int N, int K)
{
    const int m0 = blockIdx.y * 128;
    const int n0 = blockIdx.x * 128;
    GEMM1_BODY
    const int t = n0 >> 11;                 // 0=Q 1=K 2=V
    const int head = (n0 >> 7) & (HEADS - 1);
    __half* p = (t == 0) ? qh : ((t == 1) ? kh : vh);
    const float sc = (t == 0) ? 0.08838834764831845f : 1.0f;
    const int erow = m0 + wm * 32 + (lid >> 2);
    const int lcol0 = wn * 64 + (lid & 3) * 2;
#pragma unroll
    for (int mf = 0; mf < 2; mf++) {
        int tok0 = erow + mf * 16;
        int b = tok0 >> 11;
        int s0 = tok0 & 2047;
        size_t pb = ((size_t)(b * HEADS + head) * S_LEN) * HD;
#pragma unroll
        for (int nf = 0; nf < 8; nf++) {
            int lc = lcol0 + nf * 8;
            float2 bz = *(const float2*)(bias + n0 + lc);
            float v0 = (acc[mf][nf][0] + bz.x) * sc;
            float v1 = (acc[mf][nf][1] + bz.y) * sc;
            float v2 = (acc[mf][nf][2] + bz.x) * sc;
            float v3 = (acc[mf][nf][3] + bz.y) * sc;
            *(uint32_t*)(p + pb + (size_t)s0 * HD + lc)       = packh2(v0, v1);
            *(uint32_t*)(p + pb + (size_t)(s0 + 8) * HD + lc) = packh2(v2, v3);
        }
    }
}

// ---------------------------------------------------------------------------
// Tensor-core flash attention (fp16): S = Q·K^T (1 product, exact given fp16
// inputs), O += RN16(P)·V (1 product). Segment+causal mask, segment skip.
// grid (32, HEADS, BATCH), 256 threads = 8 warps (4 m-slabs x 2 key-slabs).
// ---------------------------------------------------------------------------
#define AQ_STRIDE 272                 // smem bytes per row (128 fp16 + pad)
#define SQH 0
#define SSTAGE0 17408
#define SSTAGE_BYTES 34816            // Kh, Vh
#define SKH 0
#define SVH 17408
#define SKID  87040                   // + stage*256
#define SPMAX 87552
#define SLSUM 88064
#define ATTN_SMEM 88576

__global__ __launch_bounds__(256, 1) void attn_mma_kernel(
    const int* __restrict__ ids,
    __half* __restrict__ oh,
    const __half* __restrict__ qh,
    const __half* __restrict__ kh, const __half* __restrict__ vh)
{
    extern __shared__ __align__(1024) char smem[];
    const uint32_t sb = smem_to_u32(smem);
    const int tid = threadIdx.x;
    const int lane = tid & 31, wid = tid >> 5;
    const int wm = wid >> 1, wn = wid & 1;
    const int b = blockIdx.z, h = blockIdx.y;
    const int qt = gridDim.x - 1 - blockIdx.x;       // big tiles first
    const int q0 = qt * 64;
    const size_t pbase = (size_t)(b * HEADS + h) * S_LEN * HD;
    const int* bids = ids + b * S_LEN;

    const int lr = lane >> 2;
    const int row0 = wm * 16 + lr, row1 = row0 + 8;
    const int qrow0 = q0 + row0, qrow1 = q0 + row1;
    const int qidv0 = bids[qrow0], qidv1 = bids[qrow1];
    const int qid_min = bids[q0];

    float* pmax = (float*)(smem + SPMAX);
    float* lsum = (float*)(smem + SLSUM);

    auto issue_tile = [&](int kb, int s) {
        const int k0 = kb * 64;
        const uint32_t stg = sb + SSTAGE0 + s * SSTAGE_BYTES;
#pragma unroll
        for (int j = 0; j < 4; j++) {
            int q = tid + 256 * j;
            int key = q >> 4, c16 = q & 15;
            uint32_t soff = (uint32_t)(key * AQ_STRIDE + c16 * 16);
            size_t goff = pbase + (size_t)(k0 + key) * HD + c16 * 8;
            CP_ASYNC16(stg + SKH + soff, (const char*)(kh + goff));
            CP_ASYNC16(stg + SVH + soff, (const char*)(vh + goff));
        }
        if (tid < 16)
            CP_ASYNC16(sb + SKID + s * 256 + tid * 16,
                       (const char*)(bids + k0 + tid * 4));
    };

    // ---- prologue: Q plane + tile 0 in cp.async group 0 ----
#pragma unroll
    for (int j = 0; j < 4; j++) {
        int q = tid + 256 * j;
        int key = q >> 4, c16 = q & 15;
        uint32_t soff = (uint32_t)(key * AQ_STRIDE + c16 * 16);
        size_t goff = pbase + (size_t)(q0 + key) * HD + c16 * 8;
        if (j < 2)
            CP_ASYNC16(sb + SQH + soff, (const char*)(qh + goff));
    }
    // j-loop above covers only 512 chunks of 1024 for Q (64 rows x 16 chunks);
    // fix: full Q coverage with 4 iterations over 1024 chunks at 256 threads
#pragma unroll
    for (int j = 2; j < 4; j++) {
        int q = tid + 256 * j;
        int key = q >> 4, c16 = q & 15;
        uint32_t soff = (uint32_t)(key * AQ_STRIDE + c16 * 16);
        size_t goff = pbase + (size_t)(q0 + key) * HD + c16 * 8;
        CP_ASYNC16(sb + SQH + soff, (const char*)(qh + goff));
    }
    issue_tile(0, 0);
    CP_COMMIT();

    float O[16][4];
#pragma unroll
    for (int nb = 0; nb < 16; nb++)
#pragma unroll
        for (int q = 0; q < 4; q++) O[nb][q] = 0.f;
    float m0r = -1e30f, m1r = -1e30f, l0r = 0.f, l1r = 0.f;

    const uint32_t qoffA = (uint32_t)((wm * 16 + (lane & 15)) * AQ_STRIDE + (lane >> 4) * 16);
    const uint32_t kBoff = (uint32_t)((wn * 32 + ((lane >> 1) & 8) + (lane & 7)) * AQ_STRIDE
                                      + ((lane & 8) << 1));
    const uint32_t vBoff = (uint32_t)((wn * 32 + ((lane >> 3) & 1) * 8 + (lane & 7)) * AQ_STRIDE
                                      + ((lane >> 4) & 1) * 16);

    const int nkb = qt;
    for (int kb = 0; kb <= nkb; kb++) {
        const int s = kb & 1;
        if (kb + 1 <= nkb) {
            bool skip_next = (bids[(kb + 1) * 64 + 63] < qid_min);
            if (!skip_next) issue_tile(kb + 1, s ^ 1);
        }
        CP_COMMIT();
        CP_WAIT1();
        __syncthreads();

        bool skip_cur = (bids[kb * 64 + 63] < qid_min);
        if (!skip_cur) {
            const uint32_t stg = sb + SSTAGE0 + s * SSTAGE_BYTES;
            const int k0 = kb * 64;

            // ---- S = Q·K^T (single product) ----
            float S[4][4];
#pragma unroll
            for (int nf = 0; nf < 4; nf++)
#pragma unroll
                for (int c = 0; c < 4; c++) S[nf][c] = 0.f;
#pragma unroll
            for (int ks = 0; ks < 8; ks++) {
                uint32_t ah[4];
                ldsm4(ah, sb + SQH + qoffA + ks * 32);
                uint32_t kh0[4], kh1[4];
                ldsm4(kh0, stg + SKH + kBoff + ks * 32);
                ldsm4(kh1, stg + SKH + kBoff + 16 * AQ_STRIDE + ks * 32);
                mma_f16(S[0], ah, kh0 + 0); mma_f16(S[1], ah, kh0 + 2);
                mma_f16(S[2], ah, kh1 + 0); mma_f16(S[3], ah, kh1 + 2);
            }

            // ---- mask + tile row max ----
            const uint32_t kidb = sb + SKID + s * 256;
            float mt0 = -1e30f, mt1 = -1e30f;
#pragma unroll
            for (int nf = 0; nf < 4; nf++) {
                int lc = wn * 32 + nf * 8 + 2 * (lane & 3);
                int kv0, kv1;
                asm volatile("ld.shared.v2.u32 {%0,%1}, [%2];"
                             : "=r"(kv0), "=r"(kv1) : "r"(kidb + lc * 4));
                int key = k0 + lc;
                if (key     > qrow0 || kv0 != qidv0) S[nf][0] = -1e30f;
                if (key + 1 > qrow0 || kv1 != qidv0) S[nf][1] = -1e30f;
                if (key     > qrow1 || kv0 != qidv1) S[nf][2] = -1e30f;
                if (key + 1 > qrow1 || kv1 != qidv1) S[nf][3] = -1e30f;
                mt0 = fmaxf(mt0, fmaxf(S[nf][0], S[nf][1]));
                mt1 = fmaxf(mt1, fmaxf(S[nf][2], S[nf][3]));
            }
            mt0 = fmaxf(mt0, __shfl_xor_sync(0xffffffffu, mt0, 1));
            mt0 = fmaxf(mt0, __shfl_xor_sync(0xffffffffu, mt0, 2));
            mt1 = fmaxf(mt1, __shfl_xor_sync(0xffffffffu, mt1, 1));
            mt1 = fmaxf(mt1, __shfl_xor_sync(0xffffffffu, mt1, 2));
            if ((lane & 3) == 0) {
                pmax[wn * 64 + row0] = mt0;
                pmax[wn * 64 + row1] = mt1;
            }
            __syncthreads();

            float mn0 = fmaxf(m0r, fmaxf(pmax[row0], pmax[64 + row0]));
            float mn1 = fmaxf(m1r, fmaxf(pmax[row1], pmax[64 + row1]));
            float f0 = __expf(m0r - mn0), f1 = __expf(m1r - mn1);
            m0r = mn0; m1r = mn1;

            float rs0 = 0.f, rs1 = 0.f;
#pragma unroll
            for (int nf = 0; nf < 4; nf++) {
                float p0 = (S[nf][0] < -1e29f) ? 0.f : __expf(S[nf][0] - mn0);
                float p1 = (S[nf][1] < -1e29f) ? 0.f : __expf(S[nf][1] - mn0);
                float p2 = (S[nf][2] < -1e29f) ? 0.f : __expf(S[nf][2] - mn1);
                float p3 = (S[nf][3] < -1e29f) ? 0.f : __expf(S[nf][3] - mn1);
                S[nf][0] = p0; S[nf][1] = p1; S[nf][2] = p2; S[nf][3] = p3;
                rs0 += p0 + p1; rs1 += p2 + p3;
            }
            rs0 += __shfl_xor_sync(0xffffffffu, rs0, 1);
            rs0 += __shfl_xor_sync(0xffffffffu, rs0, 2);
            rs1 += __shfl_xor_sync(0xffffffffu, rs1, 1);
            rs1 += __shfl_xor_sync(0xffffffffu, rs1, 2);
            l0r = l0r * f0 + rs0;
            l1r = l1r * f1 + rs1;

            // rescale O
#pragma unroll
            for (int nb = 0; nb < 16; nb++) {
                O[nb][0] *= f0; O[nb][1] *= f0;
                O[nb][2] *= f1; O[nb][3] *= f1;
            }

            // ---- O += RN16(P)·V (single product) ----
#pragma unroll
            for (int ks2 = 0; ks2 < 2; ks2++) {
                uint32_t ah[4];
                ah[0] = packh2(S[2 * ks2][0],     S[2 * ks2][1]);
                ah[1] = packh2(S[2 * ks2][2],     S[2 * ks2][3]);
                ah[2] = packh2(S[2 * ks2 + 1][0], S[2 * ks2 + 1][1]);
                ah[3] = packh2(S[2 * ks2 + 1][2], S[2 * ks2 + 1][3]);
                uint32_t ro = vBoff + ks2 * 16 * AQ_STRIDE;
#pragma unroll
                for (int np = 0; np < 4; np++) {
                    uint32_t vh0[4], vh1[4];
                    ldsm4t(vh0, stg + SVH + ro + (2 * np) * 32);
                    ldsm4t(vh1, stg + SVH + ro + (2 * np + 1) * 32);
                    int o0 = 4 * np;
                    mma_f16(O[o0 + 0], ah, vh0 + 0); mma_f16(O[o0 + 1], ah, vh0 + 2);
                    mma_f16(O[o0 + 2], ah, vh1 + 0); mma_f16(O[o0 + 3], ah, vh1 + 2);
                }
            }
        }
        __syncthreads();
    }

    // ---- epilogue: combine l across warp pairs, then O, then write plane ----
    if ((lane & 3) == 0) {
        lsum[wn * 64 + row0] = l0r;
        lsum[wn * 64 + row1] = l1r;
    }
    __syncthreads();
    float inv0 = 1.f / (lsum[row0] + lsum[64 + row0]);
    float inv1 = 1.f / (lsum[row1] + lsum[64 + row1]);

    if (wn == 1) {
#pragma unroll
        for (int nb = 0; nb < 16; nb++) {
            uint32_t off = (uint32_t)(wm * 8192 + lr * 512 + (nb * 8 + 2 * (lane & 3)) * 4);
            *(float2*)(smem + off) = make_float2(O[nb][0], O[nb][1]);
            *(float2*)(smem + off + 8 * 512) = make_float2(O[nb][2], O[nb][3]);
        }
    }
    __syncthreads();
    if (wn == 0) {
        const size_t g0 = ((size_t)b * S_LEN + qrow0) * DIM + h * HD;
        const size_t g1 = ((size_t)b * S_LEN + qrow1) * DIM + h * HD;
#pragma unroll
        for (int nb = 0; nb < 16; nb++) {
            int col = nb * 8 + 2 * (lane & 3);
            uint32_t off = (uint32_t)(wm * 8192 + lr * 512 + col * 4);
            float2 o0 = *(float2*)(smem + off);
            float2 o1 = *(float2*)(smem + off + 8 * 512);
            *(uint32_t*)(oh + g0 + col) =
                packh2((O[nb][0] + o0.x) * inv0, (O[nb][1] + o0.y) * inv0);
            *(uint32_t*)(oh + g1 + col) =
                packh2((O[nb][2] + o1.x) * inv1, (O[nb][3] + o1.y) * inv1);
        }
    }
}

// ---------------------------------------------------------------------------
extern "C" void kernel_launch(void* const* d_in, const int* in_sizes, int n_in,
                              void* d_out, int out_size)
{
    const float* x    = (const float*)d_in[0];   // [4,2048,2048]
    const int*   ids  = (const int*)d_in[1];     // [4,2048]
    const float* Wqkv = (const float*)d_in[2];   // [2048,6144]
    const float* bqkv = (const float*)d_in[3];   // [6144]
    const float* Wo   = (const float*)d_in[4];   // [2048,2048]
    const float* bo   = (const float*)d_in[5];   // [2048]
    float* out = (float*)d_out;

    __half *qh, *kh, *vh, *xh, *ah, *wqh, *woh;
    cudaGetSymbolAddress((void**)&qh, g_qh);
    cudaGetSymbolAddress((void**)&kh, g_kh);
    cudaGetSymbolAddress((void**)&vh, g_vh);
    cudaGetSymbolAddress((void**)&xh, g_xh);
    cudaGetSymbolAddress((void**)&ah, g_ah);
    cudaGetSymbolAddress((void**)&wqh, g_wqh);
    cudaGetSymbolAddress((void**)&woh, g_woh);

    cudaFuncSetAttribute(gemm1_out_kernel,
                         cudaFuncAttributeMaxDynamicSharedMemorySize, GSMEM_BYTES);
    cudaFuncSetAttribute(gemm1_qkv_kernel,
                         cudaFuncAttributeMaxDynamicSharedMemorySize, GSMEM_BYTES);
    cudaFuncSetAttribute(attn_mma_kernel,
                         cudaFuncAttributeMaxDynamicSharedMemorySize, ATTN_SMEM);

    const int M = BATCH * S_LEN;   // 8192

    // 0) round x, round+transpose weights (one-shot)
    round_kernel<<<1184, 256>>>(x, xh, (size_t)M * DIM / 2);
    {
        dim3 blk(32, 8);
        transpose_round_kernel<<<dim3(3 * DIM / 32, DIM / 32), blk>>>(Wqkv, wqh, DIM, 3 * DIM);
        transpose_round_kernel<<<dim3(DIM / 32, DIM / 32), blk>>>(Wo, woh, DIM, DIM);
    }
    // 1) QKV = x @ Wqkv + bqkv -> fp16 planes (Q pre-scaled), single product
    {
        dim3 grid(3 * DIM / 128, M / 128);
        gemm1_qkv_kernel<<<grid, 256, GSMEM_BYTES>>>(
            xh, wqh, bqkv, qh, kh, vh, 3 * DIM, DIM);
    }
    // 2) flash attention -> single fp16 plane
    {
        dim3 grid(S_LEN / 64, HEADS, BATCH);
        attn_mma_kernel<<<grid, 256, ATTN_SMEM>>>(ids, ah, qh, kh, vh);
    }
    // 3) out = attn @ Wo + bo  [8192, 2048] fp32, single product
    {
        dim3 grid(DIM / 128, M / 128);
        gemm1_out_kernel<<<grid, 256, GSMEM_BYTES>>>(ah, woh, bo, out, DIM, DIM);
    }
}